// round 1
// baseline (speedup 1.0000x reference)
#include <cuda_runtime.h>

#define B_DIM 4
#define S_DIM 4096
#define F_DIM 512
#define D_DIM 64

// Scratch (no cudaMalloc allowed)
__device__ float g_Q[B_DIM * S_DIM * D_DIM];
__device__ float g_K[B_DIM * S_DIM * D_DIM];
__device__ float g_ch[B_DIM * S_DIM];

typedef unsigned long long u64;

// Packed fp32x2 FMA (sm_100+): d = a*b + d  (2 MACs/op, 2x FFMA throughput)
__device__ __forceinline__ void ffma2(u64& d, u64 a, u64 b) {
    asm("fma.rn.f32x2 %0, %1, %2, %0;" : "+l"(d) : "l"(a), "l"(b));
}
__device__ __forceinline__ float2 upk(u64 v) {
    unsigned lo, hi;
    asm("mov.b64 {%0,%1}, %2;" : "=r"(lo), "=r"(hi) : "l"(v));
    return make_float2(__uint_as_float(lo), __uint_as_float(hi));
}
__device__ __forceinline__ float fast_rcp(float x) {
    float r; asm("rcp.approx.f32 %0, %1;" : "=f"(r) : "f"(x)); return r;
}

// ---------------- charge = sigmoid(feat . w + b) ----------------
__global__ __launch_bounds__(256) void charge_kernel(
    const float* __restrict__ feat, const float* __restrict__ w,
    const float* __restrict__ b)
{
    int row  = blockIdx.x * 8 + (threadIdx.x >> 5);
    int lane = threadIdx.x & 31;
    const float* fr = feat + (size_t)row * F_DIM;
    float s = 0.f;
    #pragma unroll
    for (int f = lane * 4; f < F_DIM; f += 128) {
        float4 v  = *(const float4*)(fr + f);
        float4 ww = *(const float4*)(w + f);
        s += v.x * ww.x + v.y * ww.y + v.z * ww.z + v.w * ww.w;
    }
    #pragma unroll
    for (int o = 16; o; o >>= 1) s += __shfl_xor_sync(0xffffffffu, s, o);
    if (lane == 0) g_ch[row] = 1.f / (1.f + expf(-(s + b[0])));
}

// ---------------- Q|K projection: [rows=64] x [cols=128 (Q:0..63 | K:64..127)] ----------------
__global__ __launch_bounds__(256) void proj_kernel(
    const float* __restrict__ feat, const float* __restrict__ Wq,
    const float* __restrict__ Wk)
{
    __shared__ float2 Fa[16][64];    // duplicated feature pairs, transposed+swizzled
    __shared__ float  Wb[16][128];   // combined [f][Q(64)|K(64)]

    const int t  = threadIdx.x;
    const int tx = t & 15, ty = t >> 4;
    const int rowBase = blockIdx.x * 64;

    u64 acc[4][4];
    #pragma unroll
    for (int r = 0; r < 4; ++r)
        #pragma unroll
        for (int c = 0; c < 4; ++c) acc[r][c] = 0ull;

    const int lf4 = t & 3, lrow = t >> 2;   // Fa loader mapping
    const int wd4 = t & 15, wf = t >> 4;    // W loader mapping

    for (int k0 = 0; k0 < F_DIM; k0 += 16) {
        __syncthreads();
        {
            float4 v = *(const float4*)(feat + (size_t)(rowBase + lrow) * F_DIM + k0 + lf4 * 4);
            int col = lrow ^ (lf4 << 2);
            Fa[lf4 * 4 + 0][col] = make_float2(v.x, v.x);
            Fa[lf4 * 4 + 1][col] = make_float2(v.y, v.y);
            Fa[lf4 * 4 + 2][col] = make_float2(v.z, v.z);
            Fa[lf4 * 4 + 3][col] = make_float2(v.w, v.w);
        }
        {
            float4 q = *(const float4*)(Wq + (size_t)(k0 + wf) * D_DIM + wd4 * 4);
            *(float4*)&Wb[wf][wd4 * 4] = q;
            float4 k = *(const float4*)(Wk + (size_t)(k0 + wf) * D_DIM + wd4 * 4);
            *(float4*)&Wb[wf][64 + wd4 * 4] = k;
        }
        __syncthreads();
        #pragma unroll
        for (int f = 0; f < 16; ++f) {
            const int sw = ((f >> 2) & 3) << 2;
            u64 a[4], bb[4];
            #pragma unroll
            for (int r = 0; r < 4; ++r)
                a[r] = *(const u64*)&Fa[f][(ty * 4 + r) ^ sw];
            #pragma unroll
            for (int c = 0; c < 4; ++c)
                bb[c] = *(const u64*)&Wb[f][2 * tx + 32 * c];
            #pragma unroll
            for (int r = 0; r < 4; ++r)
                #pragma unroll
                for (int c = 0; c < 4; ++c) ffma2(acc[r][c], a[r], bb[c]);
        }
    }

    #pragma unroll
    for (int r = 0; r < 4; ++r) {
        size_t row = (size_t)rowBase + ty * 4 + r;
        #pragma unroll
        for (int c = 0; c < 4; ++c) {
            int j = 2 * tx + 32 * c;
            float2 v = upk(acc[r][c]);
            if (c < 2) *(float2*)(g_Q + row * D_DIM + j) = v;
            else       *(float2*)(g_K + row * D_DIM + (j - 64)) = v;
        }
    }
}

// ---------------- energy tile 128x128, fused epilogue ----------------
__global__ __launch_bounds__(256) void energy_kernel(
    float* __restrict__ out, const float* __restrict__ loc_p)
{
    __shared__ float2 Qt[16][128];   // duplicated Q pairs, transposed+swizzled
    __shared__ float  Kt[16][128];   // transposed+swizzled K
    __shared__ float  chI[128], chJ[128];

    const int t  = threadIdx.x;
    const int tx = t & 15, ty = t >> 4;
    const int b  = blockIdx.z;
    const int iBase = blockIdx.y * 128;
    const int jBase = blockIdx.x * 128;

    if (t < 128) chI[t] = g_ch[b * S_DIM + iBase + t];
    else         chJ[t - 128] = g_ch[b * S_DIM + jBase + (t - 128)];

    u64 acc[8][4];
    #pragma unroll
    for (int r = 0; r < 8; ++r)
        #pragma unroll
        for (int c = 0; c < 4; ++c) acc[r][c] = 0ull;

    const float* Qb = g_Q + ((size_t)b * S_DIM + iBase) * D_DIM;
    const float* Kb = g_K + ((size_t)b * S_DIM + jBase) * D_DIM;

    for (int k0 = 0; k0 < D_DIM; k0 += 16) {
        __syncthreads();
        #pragma unroll
        for (int l = 0; l < 2; ++l) {
            int idx = l * 256 + t;
            int f4 = idx & 3, row = idx >> 2;
            float4 q = *(const float4*)(Qb + (size_t)row * D_DIM + k0 + f4 * 4);
            int colq = row ^ (f4 << 2);
            Qt[f4 * 4 + 0][colq] = make_float2(q.x, q.x);
            Qt[f4 * 4 + 1][colq] = make_float2(q.y, q.y);
            Qt[f4 * 4 + 2][colq] = make_float2(q.z, q.z);
            Qt[f4 * 4 + 3][colq] = make_float2(q.w, q.w);
            float4 k = *(const float4*)(Kb + (size_t)row * D_DIM + k0 + f4 * 4);
            int colk = row ^ (f4 << 3);
            Kt[f4 * 4 + 0][colk] = k.x;
            Kt[f4 * 4 + 1][colk] = k.y;
            Kt[f4 * 4 + 2][colk] = k.z;
            Kt[f4 * 4 + 3][colk] = k.w;
        }
        __syncthreads();
        #pragma unroll
        for (int f = 0; f < 16; ++f) {
            const int swq = ((f >> 2) & 3) << 2;
            const int swk = ((f >> 2) & 3) << 3;
            u64 a[8], bb[4];
            #pragma unroll
            for (int r = 0; r < 8; ++r)
                a[r] = *(const u64*)&Qt[f][(ty * 8 + r) ^ swq];
            #pragma unroll
            for (int c = 0; c < 4; ++c)
                bb[c] = *(const u64*)&Kt[f][(2 * tx + 32 * c) ^ swk];
            #pragma unroll
            for (int r = 0; r < 8; ++r)
                #pragma unroll
                for (int c = 0; c < 4; ++c) ffma2(acc[r][c], a[r], bb[c]);
        }
    }

    const float ls = loc_p[0];
    const float nscale = -0.125f;  // -1/sqrt(D=64)
    float* ob = out + ((size_t)b * S_DIM + iBase) * S_DIM + jBase;

    #pragma unroll
    for (int r = 0; r < 8; ++r) {
        int li = ty * 8 + r;
        int gi = iBase + li;
        float ci = chI[li] * nscale * ls;
        #pragma unroll
        for (int c = 0; c < 4; ++c) {
            int lj = 2 * tx + 32 * c;
            int gj = jBase + lj;
            float2 v = upk(acc[r][c]);
            float d0 = fmaxf(fabsf((float)(gi - gj)), 1.f);
            float d1 = fmaxf(fabsf((float)(gi - gj - 1)), 1.f);
            float2 o;
            o.x = v.x * ci * chJ[lj]     * fast_rcp(d0);
            o.y = v.y * ci * chJ[lj + 1] * fast_rcp(d1);
            *(float2*)(ob + (size_t)li * S_DIM + lj) = o;
        }
    }
}

extern "C" void kernel_launch(void* const* d_in, const int* in_sizes, int n_in,
                              void* d_out, int out_size) {
    const float* feat = (const float*)d_in[0];
    const float* Wq   = (const float*)d_in[1];
    const float* Wk   = (const float*)d_in[2];
    const float* wch  = (const float*)d_in[3];
    const float* bch  = (const float*)d_in[4];
    const float* ls   = (const float*)d_in[5];
    float* out = (float*)d_out;

    charge_kernel<<<(B_DIM * S_DIM) / 8, 256>>>(feat, wch, bch);
    proj_kernel<<<(B_DIM * S_DIM) / 64, 256>>>(feat, Wq, Wk);
    dim3 g2(S_DIM / 128, S_DIM / 128, B_DIM);
    energy_kernel<<<g2, 256>>>(out, ls);
}

// round 3
// speedup vs baseline: 1.7899x; 1.7899x over previous
#include <cuda_runtime.h>
#include <cuda_bf16.h>

#define B_DIM 4
#define S_DIM 4096
#define F_DIM 512
#define D_DIM 64

// ---------------- scratch (no cudaMalloc allowed) ----------------
__device__ __nv_bfloat16 g_Qhi[B_DIM * S_DIM * D_DIM];
__device__ __nv_bfloat16 g_Qlo[B_DIM * S_DIM * D_DIM];
__device__ __nv_bfloat16 g_Khi[B_DIM * S_DIM * D_DIM];
__device__ __nv_bfloat16 g_Klo[B_DIM * S_DIM * D_DIM];
__device__ float g_ch[B_DIM * S_DIM];

typedef unsigned long long u64;
typedef unsigned u32;

__device__ __forceinline__ void ffma2(u64& d, u64 a, u64 b) {
    asm("fma.rn.f32x2 %0, %1, %2, %0;" : "+l"(d) : "l"(a), "l"(b));
}
__device__ __forceinline__ float2 upk(u64 v) {
    unsigned lo, hi;
    asm("mov.b64 {%0,%1}, %2;" : "=r"(lo), "=r"(hi) : "l"(v));
    return make_float2(__uint_as_float(lo), __uint_as_float(hi));
}
__device__ __forceinline__ float fast_rcp(float x) {
    float r; asm("rcp.approx.f32 %0, %1;" : "=f"(r) : "f"(x)); return r;
}
__device__ __forceinline__ u32 smem_u32(const void* p) {
    u32 a;
    asm("{ .reg .u64 t; cvta.to.shared.u64 t, %1; cvt.u32.u64 %0, t; }" : "=r"(a) : "l"(p));
    return a;
}
__device__ __forceinline__ void ldsm_x4(u32& r0, u32& r1, u32& r2, u32& r3, u32 addr) {
    asm volatile("ldmatrix.sync.aligned.m8n8.x4.shared.b16 {%0,%1,%2,%3}, [%4];"
                 : "=r"(r0), "=r"(r1), "=r"(r2), "=r"(r3) : "r"(addr));
}
__device__ __forceinline__ void ldsm_x2(u32& r0, u32& r1, u32 addr) {
    asm volatile("ldmatrix.sync.aligned.m8n8.x2.shared.b16 {%0,%1}, [%2];"
                 : "=r"(r0), "=r"(r1) : "r"(addr));
}
__device__ __forceinline__ void mma16816(float* c, const u32* a, const u32* b) {
    asm volatile(
        "mma.sync.aligned.m16n8k16.row.col.f32.bf16.bf16.f32 "
        "{%0,%1,%2,%3}, {%4,%5,%6,%7}, {%8,%9}, {%0,%1,%2,%3};"
        : "+f"(c[0]), "+f"(c[1]), "+f"(c[2]), "+f"(c[3])
        : "r"(a[0]), "r"(a[1]), "r"(a[2]), "r"(a[3]), "r"(b[0]), "r"(b[1]));
}

// ---------------- proj + charge fused ----------------
__global__ __launch_bounds__(256) void proj_kernel(
    const float* __restrict__ feat, const float* __restrict__ Wq,
    const float* __restrict__ Wk, const float* __restrict__ wch,
    const float* __restrict__ bch)
{
    __shared__ float2 Fa[16][64];
    __shared__ float  Wb[16][128];
    __shared__ float  Wc[16];

    const int t  = threadIdx.x;
    const int tx = t & 15, ty = t >> 4;
    const int rowBase = blockIdx.x * 64;

    u64 acc[4][4];
    float csum[4] = {0.f, 0.f, 0.f, 0.f};
    #pragma unroll
    for (int r = 0; r < 4; ++r)
        #pragma unroll
        for (int c = 0; c < 4; ++c) acc[r][c] = 0ull;

    const int lf4 = t & 3, lrow = t >> 2;
    const int wd4 = t & 15, wf = t >> 4;

    for (int k0 = 0; k0 < F_DIM; k0 += 16) {
        __syncthreads();
        {
            float4 v = *(const float4*)(feat + (size_t)(rowBase + lrow) * F_DIM + k0 + lf4 * 4);
            int col = lrow ^ (lf4 << 2);
            Fa[lf4 * 4 + 0][col] = make_float2(v.x, v.x);
            Fa[lf4 * 4 + 1][col] = make_float2(v.y, v.y);
            Fa[lf4 * 4 + 2][col] = make_float2(v.z, v.z);
            Fa[lf4 * 4 + 3][col] = make_float2(v.w, v.w);
        }
        {
            float4 q = *(const float4*)(Wq + (size_t)(k0 + wf) * D_DIM + wd4 * 4);
            *(float4*)&Wb[wf][wd4 * 4] = q;
            float4 k = *(const float4*)(Wk + (size_t)(k0 + wf) * D_DIM + wd4 * 4);
            *(float4*)&Wb[wf][64 + wd4 * 4] = k;
        }
        if (t < 16) Wc[t] = wch[k0 + t];
        __syncthreads();
        #pragma unroll
        for (int f = 0; f < 16; ++f) {
            const int sw = ((f >> 2) & 3) << 2;
            u64 a[4], bb[4];
            float wcf = Wc[f];
            #pragma unroll
            for (int r = 0; r < 4; ++r) {
                a[r] = *(const u64*)&Fa[f][(ty * 4 + r) ^ sw];
                csum[r] += upk(a[r]).x * wcf;
            }
            #pragma unroll
            for (int c = 0; c < 4; ++c)
                bb[c] = *(const u64*)&Wb[f][2 * tx + 32 * c];
            #pragma unroll
            for (int r = 0; r < 4; ++r)
                #pragma unroll
                for (int c = 0; c < 4; ++c) ffma2(acc[r][c], a[r], bb[c]);
        }
    }

    #pragma unroll
    for (int r = 0; r < 4; ++r) {
        size_t row = (size_t)rowBase + ty * 4 + r;
        #pragma unroll
        for (int c = 0; c < 4; ++c) {
            int j = 2 * tx + 32 * c;
            float2 v = upk(acc[r][c]);
            __nv_bfloat16 h0 = __float2bfloat16(v.x);
            __nv_bfloat16 h1 = __float2bfloat16(v.y);
            __nv_bfloat16 l0 = __float2bfloat16(v.x - __bfloat162float(h0));
            __nv_bfloat16 l1 = __float2bfloat16(v.y - __bfloat162float(h1));
            __nv_bfloat162 hh; hh.x = h0; hh.y = h1;
            __nv_bfloat162 ll; ll.x = l0; ll.y = l1;
            if (c < 2) {
                *(__nv_bfloat162*)(g_Qhi + row * D_DIM + j) = hh;
                *(__nv_bfloat162*)(g_Qlo + row * D_DIM + j) = ll;
            } else {
                *(__nv_bfloat162*)(g_Khi + row * D_DIM + (j - 64)) = hh;
                *(__nv_bfloat162*)(g_Klo + row * D_DIM + (j - 64)) = ll;
            }
        }
    }
    if (tx == 0) {
        float bb0 = bch[0];
        #pragma unroll
        for (int r = 0; r < 4; ++r) {
            g_ch[rowBase + ty * 4 + r] = 1.f / (1.f + expf(-(csum[r] + bb0)));
        }
    }
}

// ---------------- energy: HMMA mma.sync 128x128 tile ----------------
// smem: [0..512) chI, [512..1024) chJ, [1024..) 4x16KB SW128-swizzled tiles
#define T_QHI 0
#define T_QLO 16384
#define T_KHI 32768
#define T_KLO 49152
#define SMEM_BYTES (1024 + 65536)

__global__ __launch_bounds__(256) void energy_kernel(
    float* __restrict__ out, const float* __restrict__ loc_p)
{
    extern __shared__ char smem[];
    float* chI = (float*)smem;
    float* chJ = (float*)(smem + 512);
    char* tiles = smem + 1024;
    const u32 sb_tiles = smem_u32(tiles);

    const int t = threadIdx.x;
    const int wid = t >> 5, lid = t & 31;
    const int b = blockIdx.z;
    const int iBase = blockIdx.y * 128;
    const int jBase = blockIdx.x * 128;

    if (t < 128) chI[t] = g_ch[b * S_DIM + iBase + t];
    else         chJ[t - 128] = g_ch[b * S_DIM + jBase + (t - 128)];

    // stage 4 tiles (Q hi/lo rows iBase.., K hi/lo rows jBase..), SW128 swizzle
    {
        const uint4* Qhi = (const uint4*)g_Qhi;
        const uint4* Qlo = (const uint4*)g_Qlo;
        const uint4* Khi = (const uint4*)g_Khi;
        const uint4* Klo = (const uint4*)g_Klo;
        #pragma unroll
        for (int l = 0; l < 4; ++l) {
            int idx = t + 256 * l;
            int row = idx >> 3, c16 = idx & 7;
            u32 off = row * 128 + c16 * 16;
            u32 swo = off ^ ((off >> 3) & 0x70);
            size_t qidx = (size_t)(b * S_DIM + iBase + row) * 8 + c16;
            size_t kidx = (size_t)(b * S_DIM + jBase + row) * 8 + c16;
            *(uint4*)(tiles + T_QHI + swo) = Qhi[qidx];
            *(uint4*)(tiles + T_QLO + swo) = Qlo[qidx];
            *(uint4*)(tiles + T_KHI + swo) = Khi[kidx];
            *(uint4*)(tiles + T_KLO + swo) = Klo[kidx];
        }
    }
    __syncthreads();

    // warp grid: wm in {0,1} -> 64 rows, wn in {0..3} -> 32 cols
    const int wm = wid & 1, wn = wid >> 1;

    // ldmatrix lane address components (xor term depends only on lid&7)
    const u32 lxor = ((u32)(lid & 7)) << 4;
    const u32 abase = (u32)((wm * 64) + (lid & 7) + ((lid >> 3) & 1) * 8) * 128;
    const u32 ach   = ((u32)(lid >> 4) & 1) * 16;
    const u32 bbase = (u32)((wn * 32) + (lid & 7)) * 128;
    const u32 bkh   = ((u32)(lid >> 3) & 1) * 16;

    float acc[4][4][4] = {};

    const int segA[3] = {T_QHI, T_QHI, T_QLO};
    const int segB[3] = {T_KHI, T_KLO, T_KHI};
    #pragma unroll
    for (int s = 0; s < 3; ++s) {
        const u32 aS = sb_tiles + segA[s] + abase;
        const u32 bS = sb_tiles + segB[s] + bbase;
        #pragma unroll
        for (int ks = 0; ks < 4; ++ks) {
            const u32 akb = ((u32)(ks * 32) + ach) ^ lxor;
            const u32 bkb = ((u32)(ks * 32) + bkh) ^ lxor;
            u32 af[4][4], bf[4][2];
            #pragma unroll
            for (int mt = 0; mt < 4; ++mt)
                ldsm_x4(af[mt][0], af[mt][1], af[mt][2], af[mt][3],
                        aS + mt * 2048 + akb);
            #pragma unroll
            for (int nt = 0; nt < 4; ++nt)
                ldsm_x2(bf[nt][0], bf[nt][1], bS + nt * 1024 + bkb);
            #pragma unroll
            for (int mt = 0; mt < 4; ++mt)
                #pragma unroll
                for (int nt = 0; nt < 4; ++nt)
                    mma16816(acc[mt][nt], af[mt], bf[nt]);
        }
    }

    // fused epilogue
    const float nls = -0.125f * loc_p[0];   // -1/sqrt(64) * locality_scale
    const int g = lid >> 2, tg = lid & 3;

    #pragma unroll
    for (int mt = 0; mt < 4; ++mt) {
        #pragma unroll
        for (int half = 0; half < 2; ++half) {
            int il = wm * 64 + mt * 16 + g + half * 8;
            int i = iBase + il;
            float ci = chI[il] * nls;
            float* orow = out + ((size_t)b * S_DIM + i) * S_DIM + jBase;
            #pragma unroll
            for (int nt = 0; nt < 4; ++nt) {
                int jl = wn * 32 + nt * 8 + tg * 2;
                int j = jBase + jl;
                float c0 = acc[mt][nt][half * 2 + 0];
                float c1 = acc[mt][nt][half * 2 + 1];
                float d0 = fmaxf(fabsf((float)(i - j)), 1.f);
                float d1 = fmaxf(fabsf((float)(i - j - 1)), 1.f);
                float2 o;
                o.x = c0 * ci * chJ[jl]     * fast_rcp(d0);
                o.y = c1 * ci * chJ[jl + 1] * fast_rcp(d1);
                *(float2*)(orow + jl) = o;
            }
        }
    }
}

extern "C" void kernel_launch(void* const* d_in, const int* in_sizes, int n_in,
                              void* d_out, int out_size) {
    const float* feat = (const float*)d_in[0];
    const float* Wq   = (const float*)d_in[1];
    const float* Wk   = (const float*)d_in[2];
    const float* wch  = (const float*)d_in[3];
    const float* bch  = (const float*)d_in[4];
    const float* ls   = (const float*)d_in[5];
    float* out = (float*)d_out;

    cudaFuncSetAttribute(energy_kernel, cudaFuncAttributeMaxDynamicSharedMemorySize, SMEM_BYTES);

    proj_kernel<<<(B_DIM * S_DIM) / 64, 256>>>(feat, Wq, Wk, wch, bch);
    dim3 g2(S_DIM / 128, S_DIM / 128, B_DIM);
    energy_kernel<<<g2, 256, SMEM_BYTES>>>(out, ls);
}

// round 4
// speedup vs baseline: 2.4958x; 1.3944x over previous
#include <cuda_runtime.h>
#include <cuda_bf16.h>

#define B_DIM 4
#define S_DIM 4096
#define F_DIM 512
#define D_DIM 64
#define EGRID 152
#define TOTAL_JOBS 4096   // 128 i-blocks x 32 j-tiles

// ---------------- scratch (no cudaMalloc allowed) ----------------
__device__ __nv_bfloat16 g_Qhi[B_DIM * S_DIM * D_DIM];
__device__ __nv_bfloat16 g_Qlo[B_DIM * S_DIM * D_DIM];
__device__ __nv_bfloat16 g_Khi[B_DIM * S_DIM * D_DIM];
__device__ __nv_bfloat16 g_Klo[B_DIM * S_DIM * D_DIM];

typedef unsigned long long u64;
typedef unsigned u32;

__device__ __forceinline__ float fast_rcp(float x) {
    float r; asm("rcp.approx.f32 %0, %1;" : "=f"(r) : "f"(x)); return r;
}
__device__ __forceinline__ u32 smem_u32(const void* p) {
    u32 a;
    asm("{ .reg .u64 t; cvta.to.shared.u64 t, %1; cvt.u32.u64 %0, t; }" : "=r"(a) : "l"(p));
    return a;
}
__device__ __forceinline__ void ldsm_x4(u32& r0, u32& r1, u32& r2, u32& r3, u32 addr) {
    asm volatile("ldmatrix.sync.aligned.m8n8.x4.shared.b16 {%0,%1,%2,%3}, [%4];"
                 : "=r"(r0), "=r"(r1), "=r"(r2), "=r"(r3) : "r"(addr));
}
__device__ __forceinline__ void ldsm_x2(u32& r0, u32& r1, u32 addr) {
    asm volatile("ldmatrix.sync.aligned.m8n8.x2.shared.b16 {%0,%1}, [%2];"
                 : "=r"(r0), "=r"(r1) : "r"(addr));
}
__device__ __forceinline__ void mma16816(float* c, const u32* a, const u32* b) {
    asm volatile(
        "mma.sync.aligned.m16n8k16.row.col.f32.bf16.bf16.f32 "
        "{%0,%1,%2,%3}, {%4,%5,%6,%7}, {%8,%9}, {%0,%1,%2,%3};"
        : "+f"(c[0]), "+f"(c[1]), "+f"(c[2]), "+f"(c[3])
        : "r"(a[0]), "r"(a[1]), "r"(a[2]), "r"(a[3]), "r"(b[0]), "r"(b[1]));
}
__device__ __forceinline__ void cp16(u32 dst, const void* src) {
    asm volatile("cp.async.cg.shared.global [%0], [%1], 16;" :: "r"(dst), "l"(src));
}
__device__ __forceinline__ void cp_commit() { asm volatile("cp.async.commit_group;" ::: "memory"); }
__device__ __forceinline__ void cp_wait0()  { asm volatile("cp.async.wait_group 0;" ::: "memory"); }

// split fp32 pair -> packed bf16 hi + residual lo
__device__ __forceinline__ void split2(float x, float y, u32& h, u32& l) {
    __nv_bfloat162 hh = __floats2bfloat162_rn(x, y);
    float rx = x - __bfloat162float(hh.x);
    float ry = y - __bfloat162float(hh.y);
    __nv_bfloat162 ll = __floats2bfloat162_rn(rx, ry);
    h = *(u32*)&hh; l = *(u32*)&ll;
}

// =================================================================
// proj: HMMA [128 rows] x [128 cols = Q(64)|K(64)], K-dim 512 (8 chunks of 64),
// 3-pass bf16 split, charge fused from exact fp32, all scales folded in.
// smem: Fhi 0, Flo 16K, Whi 32K, Wlo 48K, wcs 64K(+512), chRow (+512)
// =================================================================
#define P_FHI 0
#define P_FLO 16384
#define P_WHI 32768
#define P_WLO 49152
#define P_WCS 65536
#define P_CHR 66048
#define P_SMEM 66560

__global__ __launch_bounds__(256) void proj_kernel(
    const float* __restrict__ feat, const float* __restrict__ Wq,
    const float* __restrict__ Wk, const float* __restrict__ wch,
    const float* __restrict__ bch, const float* __restrict__ loc_p)
{
    extern __shared__ char smem[];
    const u32 sb = smem_u32(smem);
    float* wcs   = (float*)(smem + P_WCS);   // [2][64]
    float* chRow = (float*)(smem + P_CHR);   // [128]

    const int t = threadIdx.x;
    const int wid = t >> 5, lid = t & 31;
    const int wm = wid & 1, wn = wid >> 1;
    const int rowBase = blockIdx.x * 128;

    // loader mappings
    const int fr = t >> 1, ffo = (t & 1) * 32;       // feat: row, f-offset
    const int wj = t & 127, wh = t >> 7;             // W: j col, f-half

    if (t < 64) wcs[t] = wch[t];

    // ldmatrix lane addressing (same as validated energy kernel)
    const u32 lxor  = ((u32)(lid & 7)) << 4;
    const u32 abase = (u32)((wm * 64) + (lid & 7) + ((lid >> 3) & 1) * 8) * 128;
    const u32 ach   = ((u32)(lid >> 4) & 1) * 16;
    const u32 bbase = (u32)((wn * 32) + (lid & 7)) * 128;
    const u32 bkh   = ((u32)(lid >> 3) & 1) * 16;

    float acc[4][4][4] = {};
    float csum = 0.f;

    for (int c = 0; c < 8; ++c) {
        const int f0 = c * 64;
        __syncthreads();
        const float* wc_cur = wcs + (c & 1) * 64;

        // ---- feat tile: 128 rows x 64 f, fp32 -> hi/lo bf16 swizzled ----
        {
            const float* fp = feat + (size_t)(rowBase + fr) * F_DIM + f0 + ffo;
            #pragma unroll
            for (int a = 0; a < 4; ++a) {
                float4 v0 = *(const float4*)(fp + a * 8);
                float4 v1 = *(const float4*)(fp + a * 8 + 4);
                csum += v0.x * wc_cur[ffo + a*8 + 0] + v0.y * wc_cur[ffo + a*8 + 1]
                      + v0.z * wc_cur[ffo + a*8 + 2] + v0.w * wc_cur[ffo + a*8 + 3]
                      + v1.x * wc_cur[ffo + a*8 + 4] + v1.y * wc_cur[ffo + a*8 + 5]
                      + v1.z * wc_cur[ffo + a*8 + 6] + v1.w * wc_cur[ffo + a*8 + 7];
                uint4 H, L;
                split2(v0.x, v0.y, H.x, L.x);
                split2(v0.z, v0.w, H.y, L.y);
                split2(v1.x, v1.y, H.z, L.z);
                split2(v1.z, v1.w, H.w, L.w);
                u32 off = (u32)fr * 128 + (u32)ffo * 2 + a * 16;
                u32 swo = off ^ ((off >> 3) & 0x70);
                *(uint4*)(smem + P_FHI + swo) = H;
                *(uint4*)(smem + P_FLO + swo) = L;
            }
        }
        // ---- W tile: [j][f] transposed read, 128 j x 64 f ----
        {
            const float* wp = (wj < 64) ? (Wq + wj) : (Wk + (wj - 64));
            #pragma unroll
            for (int a = 0; a < 4; ++a) {
                float wv[8];
                #pragma unroll
                for (int k = 0; k < 8; ++k)
                    wv[k] = wp[(size_t)(f0 + wh * 32 + a * 8 + k) * D_DIM];
                uint4 H, L;
                split2(wv[0], wv[1], H.x, L.x);
                split2(wv[2], wv[3], H.y, L.y);
                split2(wv[4], wv[5], H.z, L.z);
                split2(wv[6], wv[7], H.w, L.w);
                u32 off = (u32)wj * 128 + (u32)wh * 64 + a * 16;
                u32 swo = off ^ ((off >> 3) & 0x70);
                *(uint4*)(smem + P_WHI + swo) = H;
                *(uint4*)(smem + P_WLO + swo) = L;
            }
        }
        if (t < 64 && c + 1 < 8) wcs[((c + 1) & 1) * 64 + t] = wch[f0 + 64 + t];
        __syncthreads();

        const int segA[3] = {P_FHI, P_FHI, P_FLO};
        const int segB[3] = {P_WHI, P_WLO, P_WHI};
        #pragma unroll
        for (int s = 0; s < 3; ++s) {
            const u32 aS = sb + segA[s] + abase;
            const u32 bS = sb + segB[s] + bbase;
            #pragma unroll
            for (int ks = 0; ks < 4; ++ks) {
                const u32 akb = ((u32)(ks * 32) + ach) ^ lxor;
                const u32 bkb = ((u32)(ks * 32) + bkh) ^ lxor;
                u32 af[4][4], bf[4][2];
                #pragma unroll
                for (int mt = 0; mt < 4; ++mt)
                    ldsm_x4(af[mt][0], af[mt][1], af[mt][2], af[mt][3], aS + mt * 2048 + akb);
                #pragma unroll
                for (int nt = 0; nt < 4; ++nt)
                    ldsm_x2(bf[nt][0], bf[nt][1], bS + nt * 1024 + bkb);
                #pragma unroll
                for (int mt = 0; mt < 4; ++mt)
                    #pragma unroll
                    for (int nt = 0; nt < 4; ++nt)
                        mma16816(acc[mt][nt], af[mt], bf[nt]);
            }
        }
    }

    // ---- charge: pairwise reduce, sigmoid, publish ----
    csum += __shfl_xor_sync(0xffffffffu, csum, 1);
    if (!(t & 1)) chRow[fr] = 1.f / (1.f + expf(-(csum + bch[0])));
    __syncthreads();

    // ---- epilogue: fold scales, split to bf16 hi/lo, store ----
    const float nls = -0.125f * loc_p[0];
    const int g = lid >> 2, tg = lid & 3;
    #pragma unroll
    for (int mt = 0; mt < 4; ++mt) {
        #pragma unroll
        for (int half = 0; half < 2; ++half) {
            int il = wm * 64 + mt * 16 + g + half * 8;
            size_t row = (size_t)(rowBase + il);
            float cr = chRow[il];
            #pragma unroll
            for (int nt = 0; nt < 4; ++nt) {
                int jl = wn * 32 + nt * 8 + tg * 2;
                float sc = (jl < 64) ? (nls * cr) : cr;
                float c0 = acc[mt][nt][half * 2 + 0] * sc;
                float c1 = acc[mt][nt][half * 2 + 1] * sc;
                u32 h, l;
                split2(c0, c1, h, l);
                if (jl < 64) {
                    *(u32*)&g_Qhi[row * D_DIM + jl] = h;
                    *(u32*)&g_Qlo[row * D_DIM + jl] = l;
                } else {
                    *(u32*)&g_Khi[row * D_DIM + jl - 64] = h;
                    *(u32*)&g_Klo[row * D_DIM + jl - 64] = l;
                }
            }
        }
    }
}

// =================================================================
// energy: persistent CTAs, Q tile resident, K tiles double-buffered cp.async
// smem: Qhi 0, Qlo 16K, Kbuf0 {hi 32K, lo 48K}, Kbuf1 {hi 64K, lo 80K}
// =================================================================
#define E_Q 0
#define E_K 32768
#define E_SMEM 98304

__global__ __launch_bounds__(256) void energy_kernel(float* __restrict__ out)
{
    extern __shared__ char smem[];
    const u32 sb = smem_u32(smem);

    const int t = threadIdx.x;
    const int wid = t >> 5, lid = t & 31;
    const int wm = wid & 1, wn = wid >> 1;

    const int js = (int)(((long long)blockIdx.x * TOTAL_JOBS) / EGRID);
    const int je = (int)(((long long)(blockIdx.x + 1) * TOTAL_JOBS) / EGRID);

    // loader mapping: 1024 16B atoms per 16KB tile
    const int lrow[4] = { (t) >> 3, (t + 256) >> 3, (t + 512) >> 3, (t + 768) >> 3 };
    const int lc16 = t & 7;

    const u32 lxor  = ((u32)(lid & 7)) << 4;
    const u32 abase = (u32)((wm * 64) + (lid & 7) + ((lid >> 3) & 1) * 8) * 128;
    const u32 ach   = ((u32)(lid >> 4) & 1) * 16;
    const u32 bbase = (u32)((wn * 32) + (lid & 7)) * 128;
    const u32 bkh   = ((u32)(lid >> 3) & 1) * 16;

    // prefetch K for first job into buf 0
    {
        int job = js;
        size_t krow0 = (size_t)(job >> 10) * S_DIM + (size_t)(job & 31) * 128;
        u32 kb = sb + E_K;
        #pragma unroll
        for (int l = 0; l < 4; ++l) {
            int row = lrow[l];
            u32 off = (u32)row * 128 + (u32)lc16 * 16;
            u32 swo = off ^ ((off >> 3) & 0x70);
            const char* srcH = (const char*)(g_Khi + (krow0 + row) * D_DIM) + lc16 * 16;
            const char* srcL = (const char*)(g_Klo + (krow0 + row) * D_DIM) + lc16 * 16;
            cp16(kb + swo, srcH);
            cp16(kb + 16384 + swo, srcL);
        }
        cp_commit();
    }

    int curIb = -1;

    for (int job = js; job < je; ++job) {
        const int ibg = job >> 5;
        const int jt  = job & 31;
        const int buf = (job - js) & 1;
        const u32 kb  = sb + E_K + buf * 32768;

        cp_wait0();
        __syncthreads();

        if (ibg != curIb) {
            // load Q tile (plain), rows ibg*128..
            size_t qrow0 = (size_t)ibg * 128;
            #pragma unroll
            for (int l = 0; l < 4; ++l) {
                int row = lrow[l];
                u32 off = (u32)row * 128 + (u32)lc16 * 16;
                u32 swo = off ^ ((off >> 3) & 0x70);
                *(uint4*)(smem + E_Q + swo) =
                    *(const uint4*)((const char*)(g_Qhi + (qrow0 + row) * D_DIM) + lc16 * 16);
                *(uint4*)(smem + E_Q + 16384 + swo) =
                    *(const uint4*)((const char*)(g_Qlo + (qrow0 + row) * D_DIM) + lc16 * 16);
            }
            curIb = ibg;
            __syncthreads();
        }

        // prefetch next K into other buffer (overlaps MMA below)
        if (job + 1 < je) {
            int nj = job + 1;
            size_t krow0 = (size_t)(nj >> 10) * S_DIM + (size_t)(nj & 31) * 128;
            u32 nkb = sb + E_K + (buf ^ 1) * 32768;
            #pragma unroll
            for (int l = 0; l < 4; ++l) {
                int row = lrow[l];
                u32 off = (u32)row * 128 + (u32)lc16 * 16;
                u32 swo = off ^ ((off >> 3) & 0x70);
                cp16(nkb + swo, (const char*)(g_Khi + (krow0 + row) * D_DIM) + lc16 * 16);
                cp16(nkb + 16384 + swo, (const char*)(g_Klo + (krow0 + row) * D_DIM) + lc16 * 16);
            }
            cp_commit();
        }

        // ---- MMA: 3-pass bf16 split ----
        float acc[4][4][4] = {};
        const u32 segA[3] = {sb + E_Q, sb + E_Q, sb + E_Q + 16384};
        const u32 segB[3] = {kb, kb + 16384, kb};
        #pragma unroll
        for (int s = 0; s < 3; ++s) {
            const u32 aS = segA[s] + abase;
            const u32 bS = segB[s] + bbase;
            #pragma unroll
            for (int ks = 0; ks < 4; ++ks) {
                const u32 akb = ((u32)(ks * 32) + ach) ^ lxor;
                const u32 bkb = ((u32)(ks * 32) + bkh) ^ lxor;
                u32 af[4][4], bf[4][2];
                #pragma unroll
                for (int mt = 0; mt < 4; ++mt)
                    ldsm_x4(af[mt][0], af[mt][1], af[mt][2], af[mt][3], aS + mt * 2048 + akb);
                #pragma unroll
                for (int nt = 0; nt < 4; ++nt)
                    ldsm_x2(bf[nt][0], bf[nt][1], bS + nt * 1024 + bkb);
                #pragma unroll
                for (int mt = 0; mt < 4; ++mt)
                    #pragma unroll
                    for (int nt = 0; nt < 4; ++nt)
                        mma16816(acc[mt][nt], af[mt], bf[nt]);
            }
        }

        // ---- epilogue: v * rcp(|i-j|) only (all scales folded into Q/K) ----
        const int iPos0 = (ibg & 31) * 128;
        const int jj0 = jt * 128;
        const int g = lid >> 2, tg = lid & 3;
        float* ob = out + ((size_t)ibg * 128) * S_DIM + jj0;
        #pragma unroll
        for (int mt = 0; mt < 4; ++mt) {
            #pragma unroll
            for (int half = 0; half < 2; ++half) {
                int il = wm * 64 + mt * 16 + g + half * 8;
                int ip = iPos0 + il;
                float* orow = ob + (size_t)il * S_DIM;
                #pragma unroll
                for (int nt = 0; nt < 4; ++nt) {
                    int jl = wn * 32 + nt * 8 + tg * 2;
                    int jp = jj0 + jl;
                    float d0 = fmaxf(fabsf((float)(ip - jp)), 1.f);
                    float d1 = fmaxf(fabsf((float)(ip - jp - 1)), 1.f);
                    float2 o;
                    o.x = acc[mt][nt][half * 2 + 0] * fast_rcp(d0);
                    o.y = acc[mt][nt][half * 2 + 1] * fast_rcp(d1);
                    *(float2*)(orow + jl) = o;
                }
            }
        }
    }
}

extern "C" void kernel_launch(void* const* d_in, const int* in_sizes, int n_in,
                              void* d_out, int out_size) {
    const float* feat = (const float*)d_in[0];
    const float* Wq   = (const float*)d_in[1];
    const float* Wk   = (const float*)d_in[2];
    const float* wch  = (const float*)d_in[3];
    const float* bch  = (const float*)d_in[4];
    const float* ls   = (const float*)d_in[5];
    float* out = (float*)d_out;

    cudaFuncSetAttribute(proj_kernel, cudaFuncAttributeMaxDynamicSharedMemorySize, P_SMEM);
    cudaFuncSetAttribute(energy_kernel, cudaFuncAttributeMaxDynamicSharedMemorySize, E_SMEM);

    proj_kernel<<<(B_DIM * S_DIM) / 128, 256, P_SMEM>>>(feat, Wq, Wk, wch, bch, ls);
    energy_kernel<<<EGRID, 256, E_SMEM>>>(out);
}

// round 5
// speedup vs baseline: 2.8827x; 1.1550x over previous
#include <cuda_runtime.h>
#include <cuda_bf16.h>

#define B_DIM 4
#define S_DIM 4096
#define F_DIM 512
#define D_DIM 64
#define EGRID 304
#define TOTAL_JOBS 8192   // 128 i-blocks x 64 j-tiles(64 wide)

// ---------------- scratch (no cudaMalloc allowed) ----------------
__device__ __nv_bfloat16 g_Qhi[B_DIM * S_DIM * D_DIM];
__device__ __nv_bfloat16 g_Qlo[B_DIM * S_DIM * D_DIM];
__device__ __nv_bfloat16 g_Khi[B_DIM * S_DIM * D_DIM];
__device__ __nv_bfloat16 g_Klo[B_DIM * S_DIM * D_DIM];

typedef unsigned long long u64;
typedef unsigned u32;

__device__ __forceinline__ float fast_rcp(float x) {
    float r; asm("rcp.approx.f32 %0, %1;" : "=f"(r) : "f"(x)); return r;
}
__device__ __forceinline__ u32 smem_u32(const void* p) {
    u32 a;
    asm("{ .reg .u64 t; cvta.to.shared.u64 t, %1; cvt.u32.u64 %0, t; }" : "=r"(a) : "l"(p));
    return a;
}
__device__ __forceinline__ void ldsm_x4(u32& r0, u32& r1, u32& r2, u32& r3, u32 addr) {
    asm volatile("ldmatrix.sync.aligned.m8n8.x4.shared.b16 {%0,%1,%2,%3}, [%4];"
                 : "=r"(r0), "=r"(r1), "=r"(r2), "=r"(r3) : "r"(addr));
}
__device__ __forceinline__ void ldsm_x2(u32& r0, u32& r1, u32 addr) {
    asm volatile("ldmatrix.sync.aligned.m8n8.x2.shared.b16 {%0,%1}, [%2];"
                 : "=r"(r0), "=r"(r1) : "r"(addr));
}
__device__ __forceinline__ void mma16816(float* c, const u32* a, const u32* b) {
    asm volatile(
        "mma.sync.aligned.m16n8k16.row.col.f32.bf16.bf16.f32 "
        "{%0,%1,%2,%3}, {%4,%5,%6,%7}, {%8,%9}, {%0,%1,%2,%3};"
        : "+f"(c[0]), "+f"(c[1]), "+f"(c[2]), "+f"(c[3])
        : "r"(a[0]), "r"(a[1]), "r"(a[2]), "r"(a[3]), "r"(b[0]), "r"(b[1]));
}
__device__ __forceinline__ void cp16(u32 dst, const void* src) {
    asm volatile("cp.async.cg.shared.global [%0], [%1], 16;" :: "r"(dst), "l"(src));
}
__device__ __forceinline__ void cp_commit() { asm volatile("cp.async.commit_group;" ::: "memory"); }
__device__ __forceinline__ void cp_wait0()  { asm volatile("cp.async.wait_group 0;" ::: "memory"); }

// split fp32 pair -> packed bf16 hi + residual lo
__device__ __forceinline__ void split2(float x, float y, u32& h, u32& l) {
    __nv_bfloat162 hh = __floats2bfloat162_rn(x, y);
    float rx = x - __bfloat162float(hh.x);
    float ry = y - __bfloat162float(hh.y);
    __nv_bfloat162 ll = __floats2bfloat162_rn(rx, ry);
    h = *(u32*)&hh; l = *(u32*)&ll;
}

// =================================================================
// proj: HMMA [128 rows] x [128 cols = Q(64)|K(64)] (unchanged from R4)
// =================================================================
#define P_FHI 0
#define P_FLO 16384
#define P_WHI 32768
#define P_WLO 49152
#define P_WCS 65536
#define P_CHR 66048
#define P_SMEM 66560

__global__ __launch_bounds__(256) void proj_kernel(
    const float* __restrict__ feat, const float* __restrict__ Wq,
    const float* __restrict__ Wk, const float* __restrict__ wch,
    const float* __restrict__ bch, const float* __restrict__ loc_p)
{
    extern __shared__ char smem[];
    const u32 sb = smem_u32(smem);
    float* wcs   = (float*)(smem + P_WCS);
    float* chRow = (float*)(smem + P_CHR);

    const int t = threadIdx.x;
    const int wid = t >> 5, lid = t & 31;
    const int wm = wid & 1, wn = wid >> 1;
    const int rowBase = blockIdx.x * 128;

    const int fr = t >> 1, ffo = (t & 1) * 32;
    const int wj = t & 127, wh = t >> 7;

    if (t < 64) wcs[t] = wch[t];

    const u32 lxor  = ((u32)(lid & 7)) << 4;
    const u32 abase = (u32)((wm * 64) + (lid & 7) + ((lid >> 3) & 1) * 8) * 128;
    const u32 ach   = ((u32)(lid >> 4) & 1) * 16;
    const u32 bbase = (u32)((wn * 32) + (lid & 7)) * 128;
    const u32 bkh   = ((u32)(lid >> 3) & 1) * 16;

    float acc[4][4][4] = {};
    float csum = 0.f;

    for (int c = 0; c < 8; ++c) {
        const int f0 = c * 64;
        __syncthreads();
        const float* wc_cur = wcs + (c & 1) * 64;
        {
            const float* fp = feat + (size_t)(rowBase + fr) * F_DIM + f0 + ffo;
            #pragma unroll
            for (int a = 0; a < 4; ++a) {
                float4 v0 = *(const float4*)(fp + a * 8);
                float4 v1 = *(const float4*)(fp + a * 8 + 4);
                csum += v0.x * wc_cur[ffo + a*8 + 0] + v0.y * wc_cur[ffo + a*8 + 1]
                      + v0.z * wc_cur[ffo + a*8 + 2] + v0.w * wc_cur[ffo + a*8 + 3]
                      + v1.x * wc_cur[ffo + a*8 + 4] + v1.y * wc_cur[ffo + a*8 + 5]
                      + v1.z * wc_cur[ffo + a*8 + 6] + v1.w * wc_cur[ffo + a*8 + 7];
                uint4 H, L;
                split2(v0.x, v0.y, H.x, L.x);
                split2(v0.z, v0.w, H.y, L.y);
                split2(v1.x, v1.y, H.z, L.z);
                split2(v1.z, v1.w, H.w, L.w);
                u32 off = (u32)fr * 128 + (u32)ffo * 2 + a * 16;
                u32 swo = off ^ ((off >> 3) & 0x70);
                *(uint4*)(smem + P_FHI + swo) = H;
                *(uint4*)(smem + P_FLO + swo) = L;
            }
        }
        {
            const float* wp = (wj < 64) ? (Wq + wj) : (Wk + (wj - 64));
            #pragma unroll
            for (int a = 0; a < 4; ++a) {
                float wv[8];
                #pragma unroll
                for (int k = 0; k < 8; ++k)
                    wv[k] = wp[(size_t)(f0 + wh * 32 + a * 8 + k) * D_DIM];
                uint4 H, L;
                split2(wv[0], wv[1], H.x, L.x);
                split2(wv[2], wv[3], H.y, L.y);
                split2(wv[4], wv[5], H.z, L.z);
                split2(wv[6], wv[7], H.w, L.w);
                u32 off = (u32)wj * 128 + (u32)wh * 64 + a * 16;
                u32 swo = off ^ ((off >> 3) & 0x70);
                *(uint4*)(smem + P_WHI + swo) = H;
                *(uint4*)(smem + P_WLO + swo) = L;
            }
        }
        if (t < 64 && c + 1 < 8) wcs[((c + 1) & 1) * 64 + t] = wch[f0 + 64 + t];
        __syncthreads();

        const int segA[3] = {P_FHI, P_FHI, P_FLO};
        const int segB[3] = {P_WHI, P_WLO, P_WHI};
        #pragma unroll
        for (int s = 0; s < 3; ++s) {
            const u32 aS = sb + segA[s] + abase;
            const u32 bS = sb + segB[s] + bbase;
            #pragma unroll
            for (int ks = 0; ks < 4; ++ks) {
                const u32 akb = ((u32)(ks * 32) + ach) ^ lxor;
                const u32 bkb = ((u32)(ks * 32) + bkh) ^ lxor;
                u32 af[4][4], bf[4][2];
                #pragma unroll
                for (int mt = 0; mt < 4; ++mt)
                    ldsm_x4(af[mt][0], af[mt][1], af[mt][2], af[mt][3], aS + mt * 2048 + akb);
                #pragma unroll
                for (int nt = 0; nt < 4; ++nt)
                    ldsm_x2(bf[nt][0], bf[nt][1], bS + nt * 1024 + bkb);
                #pragma unroll
                for (int mt = 0; mt < 4; ++mt)
                    #pragma unroll
                    for (int nt = 0; nt < 4; ++nt)
                        mma16816(acc[mt][nt], af[mt], bf[nt]);
            }
        }
    }

    csum += __shfl_xor_sync(0xffffffffu, csum, 1);
    if (!(t & 1)) chRow[fr] = 1.f / (1.f + expf(-(csum + bch[0])));
    __syncthreads();

    const float nls = -0.125f * loc_p[0];
    const int g = lid >> 2, tg = lid & 3;
    #pragma unroll
    for (int mt = 0; mt < 4; ++mt) {
        #pragma unroll
        for (int half = 0; half < 2; ++half) {
            int il = wm * 64 + mt * 16 + g + half * 8;
            size_t row = (size_t)(rowBase + il);
            float cr = chRow[il];
            #pragma unroll
            for (int nt = 0; nt < 4; ++nt) {
                int jl = wn * 32 + nt * 8 + tg * 2;
                float sc = (jl < 64) ? (nls * cr) : cr;
                float c0 = acc[mt][nt][half * 2 + 0] * sc;
                float c1 = acc[mt][nt][half * 2 + 1] * sc;
                u32 h, l;
                split2(c0, c1, h, l);
                if (jl < 64) {
                    *(u32*)&g_Qhi[row * D_DIM + jl] = h;
                    *(u32*)&g_Qlo[row * D_DIM + jl] = l;
                } else {
                    *(u32*)&g_Khi[row * D_DIM + jl - 64] = h;
                    *(u32*)&g_Klo[row * D_DIM + jl - 64] = l;
                }
            }
        }
    }
}

// =================================================================
// energy: persistent, 2 CTAs/SM, job tile 128(i) x 64(j)
// warp grid 4(m) x 2(n), warp tile 32x32, acc = 32 regs
// smem: Qhi 0, Qlo 16K, Kbuf0 {hi 32K, lo 40K}, Kbuf1 {hi 48K, lo 56K}
// =================================================================
#define E_Q 0
#define E_K 32768
#define E_SMEM 65536

__global__ __launch_bounds__(256, 2) void energy_kernel(float* __restrict__ out)
{
    extern __shared__ char smem[];
    const u32 sb = smem_u32(smem);

    const int t = threadIdx.x;
    const int wid = t >> 5, lid = t & 31;
    const int wm = wid & 3, wn = wid >> 2;

    const int js = (int)(((long long)blockIdx.x * TOTAL_JOBS) / EGRID);
    const int je = (int)(((long long)(blockIdx.x + 1) * TOTAL_JOBS) / EGRID);

    // loaders: Q tile 1024 atoms (4/thread), K tile 512 atoms (2/thread)
    const int lc16 = t & 7;
    const int qrow_l = t >> 3;          // + 32*l
    const int krow_l = t >> 3;          // + 32*l (l=0,1)

    const u32 lxor  = ((u32)(lid & 7)) << 4;
    const u32 abase = (u32)((wm * 32) + (lid & 7) + ((lid >> 3) & 1) * 8) * 128;
    const u32 ach   = ((u32)(lid >> 4) & 1) * 16;
    const u32 bbase = (u32)((wn * 32) + (lid & 7)) * 128;
    const u32 bkh   = ((u32)(lid >> 3) & 1) * 16;

    // prefetch K for first job into buf 0
    {
        int job = js;
        int b = job >> 11;                       // ibg = job>>6, b = ibg>>5
        size_t krow0 = (size_t)b * S_DIM + (size_t)(job & 63) * 64;
        u32 kb = sb + E_K;
        #pragma unroll
        for (int l = 0; l < 2; ++l) {
            int row = krow_l + 32 * l;
            u32 off = (u32)row * 128 + (u32)lc16 * 16;
            u32 swo = off ^ ((off >> 3) & 0x70);
            cp16(kb + swo, (const char*)(g_Khi + (krow0 + row) * D_DIM) + lc16 * 16);
            cp16(kb + 8192 + swo, (const char*)(g_Klo + (krow0 + row) * D_DIM) + lc16 * 16);
        }
        cp_commit();
    }

    int curIb = -1;

    for (int job = js; job < je; ++job) {
        const int ibg = job >> 6;
        const int jt  = job & 63;
        const int buf = (job - js) & 1;
        const u32 kb  = sb + E_K + buf * 16384;

        cp_wait0();
        __syncthreads();

        if (ibg != curIb) {
            size_t qrow0 = (size_t)ibg * 128;
            #pragma unroll
            for (int l = 0; l < 4; ++l) {
                int row = qrow_l + 32 * l;
                u32 off = (u32)row * 128 + (u32)lc16 * 16;
                u32 swo = off ^ ((off >> 3) & 0x70);
                *(uint4*)(smem + E_Q + swo) =
                    *(const uint4*)((const char*)(g_Qhi + (qrow0 + row) * D_DIM) + lc16 * 16);
                *(uint4*)(smem + E_Q + 16384 + swo) =
                    *(const uint4*)((const char*)(g_Qlo + (qrow0 + row) * D_DIM) + lc16 * 16);
            }
            curIb = ibg;
            __syncthreads();
        }

        // prefetch next K into other buffer (overlaps MMA)
        if (job + 1 < je) {
            int nj = job + 1;
            int nb = nj >> 11;
            size_t krow0 = (size_t)nb * S_DIM + (size_t)(nj & 63) * 64;
            u32 nkb = sb + E_K + (buf ^ 1) * 16384;
            #pragma unroll
            for (int l = 0; l < 2; ++l) {
                int row = krow_l + 32 * l;
                u32 off = (u32)row * 128 + (u32)lc16 * 16;
                u32 swo = off ^ ((off >> 3) & 0x70);
                cp16(nkb + swo, (const char*)(g_Khi + (krow0 + row) * D_DIM) + lc16 * 16);
                cp16(nkb + 8192 + swo, (const char*)(g_Klo + (krow0 + row) * D_DIM) + lc16 * 16);
            }
            cp_commit();
        }

        // ---- MMA: 3-pass bf16 split, warp tile 32x32 ----
        float acc[2][4][4] = {};
        const u32 segA[3] = {sb + E_Q, sb + E_Q, sb + E_Q + 16384};
        const u32 segB[3] = {kb, kb + 8192, kb};
        #pragma unroll
        for (int s = 0; s < 3; ++s) {
            const u32 aS = segA[s] + abase;
            const u32 bS = segB[s] + bbase;
            #pragma unroll
            for (int ks = 0; ks < 4; ++ks) {
                const u32 akb = ((u32)(ks * 32) + ach) ^ lxor;
                const u32 bkb = ((u32)(ks * 32) + bkh) ^ lxor;
                u32 af[2][4], bf[4][2];
                #pragma unroll
                for (int mt = 0; mt < 2; ++mt)
                    ldsm_x4(af[mt][0], af[mt][1], af[mt][2], af[mt][3], aS + mt * 2048 + akb);
                #pragma unroll
                for (int nt = 0; nt < 4; ++nt)
                    ldsm_x2(bf[nt][0], bf[nt][1], bS + nt * 1024 + bkb);
                #pragma unroll
                for (int mt = 0; mt < 2; ++mt)
                    #pragma unroll
                    for (int nt = 0; nt < 4; ++nt)
                        mma16816(acc[mt][nt], af[mt], bf[nt]);
            }
        }

        // ---- epilogue: v * rcp(|i-j|) ----
        const int iPos0 = (ibg & 31) * 128;
        const int jj0 = jt * 64;
        const int g = lid >> 2, tg = lid & 3;
        float* ob = out + ((size_t)ibg * 128) * S_DIM + jj0;
        #pragma unroll
        for (int mt = 0; mt < 2; ++mt) {
            #pragma unroll
            for (int half = 0; half < 2; ++half) {
                int il = wm * 32 + mt * 16 + g + half * 8;
                int ip = iPos0 + il;
                float* orow = ob + (size_t)il * S_DIM;
                #pragma unroll
                for (int nt = 0; nt < 4; ++nt) {
                    int jl = wn * 32 + nt * 8 + tg * 2;
                    int jp = jj0 + jl;
                    float d0 = fmaxf(fabsf((float)(ip - jp)), 1.f);
                    float d1 = fmaxf(fabsf((float)(ip - jp - 1)), 1.f);
                    float2 o;
                    o.x = acc[mt][nt][half * 2 + 0] * fast_rcp(d0);
                    o.y = acc[mt][nt][half * 2 + 1] * fast_rcp(d1);
                    *(float2*)(orow + jl) = o;
                }
            }
        }
    }
}

extern "C" void kernel_launch(void* const* d_in, const int* in_sizes, int n_in,
                              void* d_out, int out_size) {
    const float* feat = (const float*)d_in[0];
    const float* Wq   = (const float*)d_in[1];
    const float* Wk   = (const float*)d_in[2];
    const float* wch  = (const float*)d_in[3];
    const float* bch  = (const float*)d_in[4];
    const float* ls   = (const float*)d_in[5];
    float* out = (float*)d_out;

    cudaFuncSetAttribute(proj_kernel, cudaFuncAttributeMaxDynamicSharedMemorySize, P_SMEM);
    cudaFuncSetAttribute(energy_kernel, cudaFuncAttributeMaxDynamicSharedMemorySize, E_SMEM);

    proj_kernel<<<(B_DIM * S_DIM) / 128, 256, P_SMEM>>>(feat, Wq, Wk, wch, bch, ls);
    energy_kernel<<<EGRID, 256, E_SMEM>>>(out);
}

// round 6
// speedup vs baseline: 2.9117x; 1.0101x over previous
#include <cuda_runtime.h>
#include <cuda_bf16.h>

#define B_DIM 4
#define S_DIM 4096
#define F_DIM 512
#define D_DIM 64
#define EGRID 304
#define TOTAL_JOBS 8192   // 128 i-blocks x 64 j-tiles(64 wide)

// ---------------- scratch (no cudaMalloc allowed) ----------------
__device__ __nv_bfloat16 g_Qhi[B_DIM * S_DIM * D_DIM];
__device__ __nv_bfloat16 g_Qlo[B_DIM * S_DIM * D_DIM];
__device__ __nv_bfloat16 g_Khi[B_DIM * S_DIM * D_DIM];
__device__ __nv_bfloat16 g_Klo[B_DIM * S_DIM * D_DIM];
__device__ unsigned char g_Whs[8 * 16384];   // pre-swizzled W hi tiles (8 chunks)
__device__ unsigned char g_Wls[8 * 16384];   // pre-swizzled W lo tiles

typedef unsigned long long u64;
typedef unsigned u32;

__device__ __forceinline__ float fast_rcp(float x) {
    float r; asm("rcp.approx.f32 %0, %1;" : "=f"(r) : "f"(x)); return r;
}
__device__ __forceinline__ u32 smem_u32(const void* p) {
    u32 a;
    asm("{ .reg .u64 t; cvta.to.shared.u64 t, %1; cvt.u32.u64 %0, t; }" : "=r"(a) : "l"(p));
    return a;
}
__device__ __forceinline__ void ldsm_x4(u32& r0, u32& r1, u32& r2, u32& r3, u32 addr) {
    asm volatile("ldmatrix.sync.aligned.m8n8.x4.shared.b16 {%0,%1,%2,%3}, [%4];"
                 : "=r"(r0), "=r"(r1), "=r"(r2), "=r"(r3) : "r"(addr));
}
__device__ __forceinline__ void ldsm_x2(u32& r0, u32& r1, u32 addr) {
    asm volatile("ldmatrix.sync.aligned.m8n8.x2.shared.b16 {%0,%1}, [%2];"
                 : "=r"(r0), "=r"(r1) : "r"(addr));
}
__device__ __forceinline__ void mma16816(float* c, const u32* a, const u32* b) {
    asm volatile(
        "mma.sync.aligned.m16n8k16.row.col.f32.bf16.bf16.f32 "
        "{%0,%1,%2,%3}, {%4,%5,%6,%7}, {%8,%9}, {%0,%1,%2,%3};"
        : "+f"(c[0]), "+f"(c[1]), "+f"(c[2]), "+f"(c[3])
        : "r"(a[0]), "r"(a[1]), "r"(a[2]), "r"(a[3]), "r"(b[0]), "r"(b[1]));
}
__device__ __forceinline__ void cp16(u32 dst, const void* src) {
    asm volatile("cp.async.cg.shared.global [%0], [%1], 16;" :: "r"(dst), "l"(src));
}
__device__ __forceinline__ void cp_commit() { asm volatile("cp.async.commit_group;" ::: "memory"); }
__device__ __forceinline__ void cp_wait0()  { asm volatile("cp.async.wait_group 0;" ::: "memory"); }
__device__ __forceinline__ void cp_wait1()  { asm volatile("cp.async.wait_group 1;" ::: "memory"); }

// split fp32 pair -> packed bf16 hi + residual lo
__device__ __forceinline__ void split2(float x, float y, u32& h, u32& l) {
    __nv_bfloat162 hh = __floats2bfloat162_rn(x, y);
    float rx = x - __bfloat162float(hh.x);
    float ry = y - __bfloat162float(hh.y);
    __nv_bfloat162 ll = __floats2bfloat162_rn(rx, ry);
    h = *(u32*)&hh; l = *(u32*)&ll;
}

// =================================================================
// W setup: split Wq|Wk to bf16 hi/lo, pre-swizzled 16KB tile images
// image c: row j (0..127, Q|K), 64 f values (chunk c), 128B/row, SW128
// =================================================================
__global__ __launch_bounds__(256) void wsetup_kernel(
    const float* __restrict__ Wq, const float* __restrict__ Wk)
{
    int idx = blockIdx.x * 256 + threadIdx.x;   // 8192 items
    int c = idx >> 10;
    int j = (idx >> 3) & 127;
    int a = idx & 7;
    const float* wp = (j < 64) ? (Wq + j) : (Wk + (j - 64));
    int f0 = c * 64 + a * 8;
    float wv[8];
    #pragma unroll
    for (int k = 0; k < 8; ++k) wv[k] = wp[(size_t)(f0 + k) * D_DIM];
    uint4 H, L;
    split2(wv[0], wv[1], H.x, L.x);
    split2(wv[2], wv[3], H.y, L.y);
    split2(wv[4], wv[5], H.z, L.z);
    split2(wv[6], wv[7], H.w, L.w);
    u32 off = (u32)j * 128 + (u32)a * 16;
    u32 swo = off ^ ((off >> 3) & 0x70);
    *(uint4*)(g_Whs + c * 16384 + swo) = H;
    *(uint4*)(g_Wls + c * 16384 + swo) = L;
}

// =================================================================
// proj: HMMA [128 rows] x [128 cols = Q(64)|K(64)], fused-pass fragments,
// W tiles double-buffered via cp.async from pre-swizzled global images.
// smem: Fhi 0, Flo 16K, Wbuf0 {hi 32K, lo 48K}, Wbuf1 {hi 64K, lo 80K},
//       wcs 96K, chRow +512
// =================================================================
#define P_FHI 0
#define P_FLO 16384
#define P_W   32768
#define P_WCS 98304
#define P_CHR 98816
#define P_SMEM 99328

__global__ __launch_bounds__(256) void proj_kernel(
    const float* __restrict__ feat, const float* __restrict__ wch,
    const float* __restrict__ bch, const float* __restrict__ loc_p)
{
    extern __shared__ char smem[];
    const u32 sb = smem_u32(smem);
    float* wcs   = (float*)(smem + P_WCS);
    float* chRow = (float*)(smem + P_CHR);

    const int t = threadIdx.x;
    const int wid = t >> 5, lid = t & 31;
    const int wm = wid & 1, wn = wid >> 1;
    const int rowBase = blockIdx.x * 128;

    const int fr = t >> 1, ffo = (t & 1) * 32;
    const int watom = t * 16;      // W copy: 4KB per 256-thread pass

    if (t < 64) wcs[t] = wch[t];

    const u32 lxor  = ((u32)(lid & 7)) << 4;
    const u32 abase = (u32)((wm * 64) + (lid & 7) + ((lid >> 3) & 1) * 8) * 128;
    const u32 ach   = ((u32)(lid >> 4) & 1) * 16;
    const u32 bbase = (u32)((wn * 32) + (lid & 7)) * 128;
    const u32 bkh   = ((u32)(lid >> 3) & 1) * 16;

    float acc[4][4][4] = {};
    float csum = 0.f;

    // prefetch W chunk 0 into buf 0
    {
        u32 wb = sb + P_W;
        #pragma unroll
        for (int a = 0; a < 4; ++a) {
            cp16(wb + watom + a * 4096, g_Whs + watom + a * 4096);
            cp16(wb + 16384 + watom + a * 4096, g_Wls + watom + a * 4096);
        }
        cp_commit();
    }

    for (int c = 0; c < 8; ++c) {
        const int f0 = c * 64;
        const u32 wb = sb + P_W + (c & 1) * 32768;
        __syncthreads();
        const float* wc_cur = wcs + (c & 1) * 64;
        // ---- feat tile: fp32 -> hi/lo bf16 swizzled + charge partial ----
        {
            const float* fp = feat + (size_t)(rowBase + fr) * F_DIM + f0 + ffo;
            #pragma unroll
            for (int a = 0; a < 4; ++a) {
                float4 v0 = *(const float4*)(fp + a * 8);
                float4 v1 = *(const float4*)(fp + a * 8 + 4);
                csum += v0.x * wc_cur[ffo + a*8 + 0] + v0.y * wc_cur[ffo + a*8 + 1]
                      + v0.z * wc_cur[ffo + a*8 + 2] + v0.w * wc_cur[ffo + a*8 + 3]
                      + v1.x * wc_cur[ffo + a*8 + 4] + v1.y * wc_cur[ffo + a*8 + 5]
                      + v1.z * wc_cur[ffo + a*8 + 6] + v1.w * wc_cur[ffo + a*8 + 7];
                uint4 H, L;
                split2(v0.x, v0.y, H.x, L.x);
                split2(v0.z, v0.w, H.y, L.y);
                split2(v1.x, v1.y, H.z, L.z);
                split2(v1.z, v1.w, H.w, L.w);
                u32 off = (u32)fr * 128 + (u32)ffo * 2 + a * 16;
                u32 swo = off ^ ((off >> 3) & 0x70);
                *(uint4*)(smem + P_FHI + swo) = H;
                *(uint4*)(smem + P_FLO + swo) = L;
            }
        }
        // prefetch next W chunk into other buffer
        if (c + 1 < 8) {
            u32 nwb = sb + P_W + ((c + 1) & 1) * 32768;
            const unsigned char* gh = g_Whs + (c + 1) * 16384;
            const unsigned char* gl = g_Wls + (c + 1) * 16384;
            #pragma unroll
            for (int a = 0; a < 4; ++a) {
                cp16(nwb + watom + a * 4096, gh + watom + a * 4096);
                cp16(nwb + 16384 + watom + a * 4096, gl + watom + a * 4096);
            }
            cp_commit();
            cp_wait1();
        } else {
            cp_wait0();
        }
        if (t < 64 && c + 1 < 8) wcs[((c + 1) & 1) * 64 + t] = wch[f0 + 64 + t];
        __syncthreads();

        // ---- fused 3-pass MMA: per kstep load each fragment once ----
        #pragma unroll
        for (int ks = 0; ks < 4; ++ks) {
            const u32 akb = ((u32)(ks * 32) + ach) ^ lxor;
            const u32 bkb = ((u32)(ks * 32) + bkh) ^ lxor;
            u32 afH[4][4], afL[4][4], bfH[4][2], bfL[4][2];
            #pragma unroll
            for (int mt = 0; mt < 4; ++mt)
                ldsm_x4(afH[mt][0], afH[mt][1], afH[mt][2], afH[mt][3],
                        sb + P_FHI + abase + mt * 2048 + akb);
            #pragma unroll
            for (int nt = 0; nt < 4; ++nt)
                ldsm_x2(bfH[nt][0], bfH[nt][1], wb + bbase + nt * 1024 + bkb);
            #pragma unroll
            for (int mt = 0; mt < 4; ++mt)
                #pragma unroll
                for (int nt = 0; nt < 4; ++nt)
                    mma16816(acc[mt][nt], afH[mt], bfH[nt]);
            #pragma unroll
            for (int nt = 0; nt < 4; ++nt)
                ldsm_x2(bfL[nt][0], bfL[nt][1], wb + 16384 + bbase + nt * 1024 + bkb);
            #pragma unroll
            for (int mt = 0; mt < 4; ++mt)
                #pragma unroll
                for (int nt = 0; nt < 4; ++nt)
                    mma16816(acc[mt][nt], afH[mt], bfL[nt]);
            #pragma unroll
            for (int mt = 0; mt < 4; ++mt)
                ldsm_x4(afL[mt][0], afL[mt][1], afL[mt][2], afL[mt][3],
                        sb + P_FLO + abase + mt * 2048 + akb);
            #pragma unroll
            for (int mt = 0; mt < 4; ++mt)
                #pragma unroll
                for (int nt = 0; nt < 4; ++nt)
                    mma16816(acc[mt][nt], afL[mt], bfH[nt]);
        }
    }

    csum += __shfl_xor_sync(0xffffffffu, csum, 1);
    if (!(t & 1)) chRow[fr] = 1.f / (1.f + expf(-(csum + bch[0])));
    __syncthreads();

    const float nls = -0.125f * loc_p[0];
    const int g = lid >> 2, tg = lid & 3;
    #pragma unroll
    for (int mt = 0; mt < 4; ++mt) {
        #pragma unroll
        for (int half = 0; half < 2; ++half) {
            int il = wm * 64 + mt * 16 + g + half * 8;
            size_t row = (size_t)(rowBase + il);
            float cr = chRow[il];
            #pragma unroll
            for (int nt = 0; nt < 4; ++nt) {
                int jl = wn * 32 + nt * 8 + tg * 2;
                float sc = (jl < 64) ? (nls * cr) : cr;
                float c0 = acc[mt][nt][half * 2 + 0] * sc;
                float c1 = acc[mt][nt][half * 2 + 1] * sc;
                u32 h, l;
                split2(c0, c1, h, l);
                if (jl < 64) {
                    *(u32*)&g_Qhi[row * D_DIM + jl] = h;
                    *(u32*)&g_Qlo[row * D_DIM + jl] = l;
                } else {
                    *(u32*)&g_Khi[row * D_DIM + jl - 64] = h;
                    *(u32*)&g_Klo[row * D_DIM + jl - 64] = l;
                }
            }
        }
    }
}

// =================================================================
// energy: persistent, 2 CTAs/SM, job tile 128(i) x 64(j),
// fused 3-pass fragments (LDSM -33%), double-buffered K cp.async
// =================================================================
#define E_Q 0
#define E_K 32768
#define E_SMEM 65536

__global__ __launch_bounds__(256, 2) void energy_kernel(float* __restrict__ out)
{
    extern __shared__ char smem[];
    const u32 sb = smem_u32(smem);

    const int t = threadIdx.x;
    const int wid = t >> 5, lid = t & 31;
    const int wm = wid & 3, wn = wid >> 2;

    const int js = (int)(((long long)blockIdx.x * TOTAL_JOBS) / EGRID);
    const int je = (int)(((long long)(blockIdx.x + 1) * TOTAL_JOBS) / EGRID);

    const int lc16 = t & 7;
    const int qrow_l = t >> 3;
    const int krow_l = t >> 3;

    const u32 lxor  = ((u32)(lid & 7)) << 4;
    const u32 abase = (u32)((wm * 32) + (lid & 7) + ((lid >> 3) & 1) * 8) * 128;
    const u32 ach   = ((u32)(lid >> 4) & 1) * 16;
    const u32 bbase = (u32)((wn * 32) + (lid & 7)) * 128;
    const u32 bkh   = ((u32)(lid >> 3) & 1) * 16;

    // prefetch K for first job into buf 0
    {
        int job = js;
        int b = job >> 11;
        size_t krow0 = (size_t)b * S_DIM + (size_t)(job & 63) * 64;
        u32 kb = sb + E_K;
        #pragma unroll
        for (int l = 0; l < 2; ++l) {
            int row = krow_l + 32 * l;
            u32 off = (u32)row * 128 + (u32)lc16 * 16;
            u32 swo = off ^ ((off >> 3) & 0x70);
            cp16(kb + swo, (const char*)(g_Khi + (krow0 + row) * D_DIM) + lc16 * 16);
            cp16(kb + 8192 + swo, (const char*)(g_Klo + (krow0 + row) * D_DIM) + lc16 * 16);
        }
        cp_commit();
    }

    int curIb = -1;

    for (int job = js; job < je; ++job) {
        const int ibg = job >> 6;
        const int jt  = job & 63;
        const int buf = (job - js) & 1;
        const u32 kb  = sb + E_K + buf * 16384;

        cp_wait0();
        __syncthreads();

        if (ibg != curIb) {
            size_t qrow0 = (size_t)ibg * 128;
            #pragma unroll
            for (int l = 0; l < 4; ++l) {
                int row = qrow_l + 32 * l;
                u32 off = (u32)row * 128 + (u32)lc16 * 16;
                u32 swo = off ^ ((off >> 3) & 0x70);
                *(uint4*)(smem + E_Q + swo) =
                    *(const uint4*)((const char*)(g_Qhi + (qrow0 + row) * D_DIM) + lc16 * 16);
                *(uint4*)(smem + E_Q + 16384 + swo) =
                    *(const uint4*)((const char*)(g_Qlo + (qrow0 + row) * D_DIM) + lc16 * 16);
            }
            curIb = ibg;
            __syncthreads();
        }

        // prefetch next K into other buffer (overlaps MMA)
        if (job + 1 < je) {
            int nj = job + 1;
            int nb = nj >> 11;
            size_t krow0 = (size_t)nb * S_DIM + (size_t)(nj & 63) * 64;
            u32 nkb = sb + E_K + (buf ^ 1) * 16384;
            #pragma unroll
            for (int l = 0; l < 2; ++l) {
                int row = krow_l + 32 * l;
                u32 off = (u32)row * 128 + (u32)lc16 * 16;
                u32 swo = off ^ ((off >> 3) & 0x70);
                cp16(nkb + swo, (const char*)(g_Khi + (krow0 + row) * D_DIM) + lc16 * 16);
                cp16(nkb + 8192 + swo, (const char*)(g_Klo + (krow0 + row) * D_DIM) + lc16 * 16);
            }
            cp_commit();
        }

        // ---- fused 3-pass MMA, warp tile 32x32 ----
        float acc[2][4][4] = {};
        #pragma unroll
        for (int ks = 0; ks < 4; ++ks) {
            const u32 akb = ((u32)(ks * 32) + ach) ^ lxor;
            const u32 bkb = ((u32)(ks * 32) + bkh) ^ lxor;
            u32 afH[2][4], afL[2][4], bfH[4][2], bfL[4][2];
            #pragma unroll
            for (int mt = 0; mt < 2; ++mt)
                ldsm_x4(afH[mt][0], afH[mt][1], afH[mt][2], afH[mt][3],
                        sb + E_Q + abase + mt * 2048 + akb);
            #pragma unroll
            for (int nt = 0; nt < 4; ++nt)
                ldsm_x2(bfH[nt][0], bfH[nt][1], kb + bbase + nt * 1024 + bkb);
            #pragma unroll
            for (int mt = 0; mt < 2; ++mt)
                #pragma unroll
                for (int nt = 0; nt < 4; ++nt)
                    mma16816(acc[mt][nt], afH[mt], bfH[nt]);
            #pragma unroll
            for (int nt = 0; nt < 4; ++nt)
                ldsm_x2(bfL[nt][0], bfL[nt][1], kb + 8192 + bbase + nt * 1024 + bkb);
            #pragma unroll
            for (int mt = 0; mt < 2; ++mt)
                #pragma unroll
                for (int nt = 0; nt < 4; ++nt)
                    mma16816(acc[mt][nt], afH[mt], bfL[nt]);
            #pragma unroll
            for (int mt = 0; mt < 2; ++mt)
                ldsm_x4(afL[mt][0], afL[mt][1], afL[mt][2], afL[mt][3],
                        sb + E_Q + 16384 + abase + mt * 2048 + akb);
            #pragma unroll
            for (int mt = 0; mt < 2; ++mt)
                #pragma unroll
                for (int nt = 0; nt < 4; ++nt)
                    mma16816(acc[mt][nt], afL[mt], bfH[nt]);
        }

        // ---- epilogue: v * rcp(|i-j|) ----
        const int iPos0 = (ibg & 31) * 128;
        const int jj0 = jt * 64;
        const int g = lid >> 2, tg = lid & 3;
        float* ob = out + ((size_t)ibg * 128) * S_DIM + jj0;
        #pragma unroll
        for (int mt = 0; mt < 2; ++mt) {
            #pragma unroll
            for (int half = 0; half < 2; ++half) {
                int il = wm * 32 + mt * 16 + g + half * 8;
                int ip = iPos0 + il;
                float* orow = ob + (size_t)il * S_DIM;
                #pragma unroll
                for (int nt = 0; nt < 4; ++nt) {
                    int jl = wn * 32 + nt * 8 + tg * 2;
                    int jp = jj0 + jl;
                    float d0 = fmaxf(fabsf((float)(ip - jp)), 1.f);
                    float d1 = fmaxf(fabsf((float)(ip - jp - 1)), 1.f);
                    float2 o;
                    o.x = acc[mt][nt][half * 2 + 0] * fast_rcp(d0);
                    o.y = acc[mt][nt][half * 2 + 1] * fast_rcp(d1);
                    *(float2*)(orow + jl) = o;
                }
            }
        }
    }
}

extern "C" void kernel_launch(void* const* d_in, const int* in_sizes, int n_in,
                              void* d_out, int out_size) {
    const float* feat = (const float*)d_in[0];
    const float* Wq   = (const float*)d_in[1];
    const float* Wk   = (const float*)d_in[2];
    const float* wch  = (const float*)d_in[3];
    const float* bch  = (const float*)d_in[4];
    const float* ls   = (const float*)d_in[5];
    float* out = (float*)d_out;

    cudaFuncSetAttribute(proj_kernel, cudaFuncAttributeMaxDynamicSharedMemorySize, P_SMEM);
    cudaFuncSetAttribute(energy_kernel, cudaFuncAttributeMaxDynamicSharedMemorySize, E_SMEM);

    wsetup_kernel<<<32, 256>>>(Wq, Wk);
    proj_kernel<<<(B_DIM * S_DIM) / 128, 256, P_SMEM>>>(feat, wch, bch, ls);
    energy_kernel<<<EGRID, 256, E_SMEM>>>(out);
}

// round 7
// speedup vs baseline: 3.0715x; 1.0549x over previous
#include <cuda_runtime.h>
#include <cuda_bf16.h>

#define B_DIM 4
#define S_DIM 4096
#define F_DIM 512
#define D_DIM 64
#define EGRID 608
#define TOTAL_JOBS 16384   // 256 i-blocks(64) x 64 j-tiles(64)

// ---------------- scratch (no cudaMalloc allowed) ----------------
__device__ __nv_bfloat16 g_Qhi[B_DIM * S_DIM * D_DIM];
__device__ __nv_bfloat16 g_Qlo[B_DIM * S_DIM * D_DIM];
__device__ __nv_bfloat16 g_Khi[B_DIM * S_DIM * D_DIM];
__device__ __nv_bfloat16 g_Klo[B_DIM * S_DIM * D_DIM];
__device__ unsigned char g_Whs[8 * 16384];   // pre-swizzled W hi tiles
__device__ unsigned char g_Wls[8 * 16384];   // pre-swizzled W lo tiles

typedef unsigned long long u64;
typedef unsigned u32;

__device__ __forceinline__ float fast_rcp(float x) {
    float r; asm("rcp.approx.f32 %0, %1;" : "=f"(r) : "f"(x)); return r;
}
__device__ __forceinline__ u32 smem_u32(const void* p) {
    u32 a;
    asm("{ .reg .u64 t; cvta.to.shared.u64 t, %1; cvt.u32.u64 %0, t; }" : "=r"(a) : "l"(p));
    return a;
}
__device__ __forceinline__ void ldsm_x4(u32& r0, u32& r1, u32& r2, u32& r3, u32 addr) {
    asm volatile("ldmatrix.sync.aligned.m8n8.x4.shared.b16 {%0,%1,%2,%3}, [%4];"
                 : "=r"(r0), "=r"(r1), "=r"(r2), "=r"(r3) : "r"(addr));
}
__device__ __forceinline__ void ldsm_x2(u32& r0, u32& r1, u32 addr) {
    asm volatile("ldmatrix.sync.aligned.m8n8.x2.shared.b16 {%0,%1}, [%2];"
                 : "=r"(r0), "=r"(r1) : "r"(addr));
}
__device__ __forceinline__ void mma16816(float* c, const u32* a, const u32* b) {
    asm volatile(
        "mma.sync.aligned.m16n8k16.row.col.f32.bf16.bf16.f32 "
        "{%0,%1,%2,%3}, {%4,%5,%6,%7}, {%8,%9}, {%0,%1,%2,%3};"
        : "+f"(c[0]), "+f"(c[1]), "+f"(c[2]), "+f"(c[3])
        : "r"(a[0]), "r"(a[1]), "r"(a[2]), "r"(a[3]), "r"(b[0]), "r"(b[1]));
}
__device__ __forceinline__ void cp16(u32 dst, const void* src) {
    asm volatile("cp.async.cg.shared.global [%0], [%1], 16;" :: "r"(dst), "l"(src));
}
__device__ __forceinline__ void cp_commit() { asm volatile("cp.async.commit_group;" ::: "memory"); }
__device__ __forceinline__ void cp_wait0()  { asm volatile("cp.async.wait_group 0;" ::: "memory"); }
__device__ __forceinline__ void cp_wait1()  { asm volatile("cp.async.wait_group 1;" ::: "memory"); }

__device__ __forceinline__ void split2(float x, float y, u32& h, u32& l) {
    __nv_bfloat162 hh = __floats2bfloat162_rn(x, y);
    float rx = x - __bfloat162float(hh.x);
    float ry = y - __bfloat162float(hh.y);
    __nv_bfloat162 ll = __floats2bfloat162_rn(rx, ry);
    h = *(u32*)&hh; l = *(u32*)&ll;
}

// =================================================================
// W setup: split Wq|Wk to bf16 hi/lo pre-swizzled tile images
// =================================================================
__global__ __launch_bounds__(256) void wsetup_kernel(
    const float* __restrict__ Wq, const float* __restrict__ Wk)
{
    int idx = blockIdx.x * 256 + threadIdx.x;   // 8192 items
    int c = idx >> 10;
    int j = (idx >> 3) & 127;
    int a = idx & 7;
    const float* wp = (j < 64) ? (Wq + j) : (Wk + (j - 64));
    int f0 = c * 64 + a * 8;
    float wv[8];
    #pragma unroll
    for (int k = 0; k < 8; ++k) wv[k] = wp[(size_t)(f0 + k) * D_DIM];
    uint4 H, L;
    split2(wv[0], wv[1], H.x, L.x);
    split2(wv[2], wv[3], H.y, L.y);
    split2(wv[4], wv[5], H.z, L.z);
    split2(wv[6], wv[7], H.w, L.w);
    u32 off = (u32)j * 128 + (u32)a * 16;
    u32 swo = off ^ ((off >> 3) & 0x70);
    *(uint4*)(g_Whs + c * 16384 + swo) = H;
    *(uint4*)(g_Wls + c * 16384 + swo) = L;
}

// =================================================================
// proj: 64-row tiles, grid 256, 2 CTAs/SM. HMMA [64] x [128 = Q|K].
// smem: Fhi 0(8K), Flo 8K, Wbuf 16K(2x32K), wcs 80K, chRow +512
// =================================================================
#define P_FHI 0
#define P_FLO 8192
#define P_W   16384
#define P_WCS 81920
#define P_CHR 82432
#define P_SMEM 82944

__global__ __launch_bounds__(256, 2) void proj_kernel(
    const float* __restrict__ feat, const float* __restrict__ wch,
    const float* __restrict__ bch, const float* __restrict__ loc_p)
{
    extern __shared__ char smem[];
    const u32 sb = smem_u32(smem);
    float* wcs   = (float*)(smem + P_WCS);
    float* chRow = (float*)(smem + P_CHR);

    const int t = threadIdx.x;
    const int wid = t >> 5, lid = t & 31;
    const int wm = wid & 1, wn = wid >> 1;
    const int rowBase = blockIdx.x * 64;

    const int fr = t >> 2, ffo = (t & 3) * 16;
    const int watom = t * 16;

    if (t < 64) wcs[t] = wch[t];

    const u32 lxor  = ((u32)(lid & 7)) << 4;
    const u32 abase = (u32)((wm * 32) + (lid & 7) + ((lid >> 3) & 1) * 8) * 128;
    const u32 ach   = ((u32)(lid >> 4) & 1) * 16;
    const u32 bbase = (u32)((wn * 32) + (lid & 7)) * 128;
    const u32 bkh   = ((u32)(lid >> 3) & 1) * 16;

    float acc[2][4][4] = {};
    float csum = 0.f;

    // prefetch W chunk 0 into buf 0
    {
        u32 wb = sb + P_W;
        #pragma unroll
        for (int a = 0; a < 4; ++a) {
            cp16(wb + watom + a * 4096, g_Whs + watom + a * 4096);
            cp16(wb + 16384 + watom + a * 4096, g_Wls + watom + a * 4096);
        }
        cp_commit();
    }

    for (int c = 0; c < 8; ++c) {
        const int f0 = c * 64;
        const u32 wb = sb + P_W + (c & 1) * 32768;
        __syncthreads();
        const float* wc_cur = wcs + (c & 1) * 64;
        // ---- feat tile: 64 rows x 64 f, fp32 -> hi/lo + charge partial ----
        {
            const float* fp = feat + (size_t)(rowBase + fr) * F_DIM + f0 + ffo;
            #pragma unroll
            for (int a = 0; a < 2; ++a) {
                float4 v0 = *(const float4*)(fp + a * 8);
                float4 v1 = *(const float4*)(fp + a * 8 + 4);
                csum += v0.x * wc_cur[ffo + a*8 + 0] + v0.y * wc_cur[ffo + a*8 + 1]
                      + v0.z * wc_cur[ffo + a*8 + 2] + v0.w * wc_cur[ffo + a*8 + 3]
                      + v1.x * wc_cur[ffo + a*8 + 4] + v1.y * wc_cur[ffo + a*8 + 5]
                      + v1.z * wc_cur[ffo + a*8 + 6] + v1.w * wc_cur[ffo + a*8 + 7];
                uint4 H, L;
                split2(v0.x, v0.y, H.x, L.x);
                split2(v0.z, v0.w, H.y, L.y);
                split2(v1.x, v1.y, H.z, L.z);
                split2(v1.z, v1.w, H.w, L.w);
                u32 off = (u32)fr * 128 + (u32)(ffo + a * 8) * 2;
                u32 swo = off ^ ((off >> 3) & 0x70);
                *(uint4*)(smem + P_FHI + swo) = H;
                *(uint4*)(smem + P_FLO + swo) = L;
            }
        }
        // prefetch next W chunk
        if (c + 1 < 8) {
            u32 nwb = sb + P_W + ((c + 1) & 1) * 32768;
            const unsigned char* gh = g_Whs + (c + 1) * 16384;
            const unsigned char* gl = g_Wls + (c + 1) * 16384;
            #pragma unroll
            for (int a = 0; a < 4; ++a) {
                cp16(nwb + watom + a * 4096, gh + watom + a * 4096);
                cp16(nwb + 16384 + watom + a * 4096, gl + watom + a * 4096);
            }
            cp_commit();
            cp_wait1();
        } else {
            cp_wait0();
        }
        if (t < 64 && c + 1 < 8) wcs[((c + 1) & 1) * 64 + t] = wch[f0 + 64 + t];
        __syncthreads();

        // ---- fused 3-pass MMA ----
        #pragma unroll
        for (int ks = 0; ks < 4; ++ks) {
            const u32 akb = ((u32)(ks * 32) + ach) ^ lxor;
            const u32 bkb = ((u32)(ks * 32) + bkh) ^ lxor;
            u32 afH[2][4], afL[2][4], bfH[4][2], bfL[4][2];
            #pragma unroll
            for (int mt = 0; mt < 2; ++mt)
                ldsm_x4(afH[mt][0], afH[mt][1], afH[mt][2], afH[mt][3],
                        sb + P_FHI + abase + mt * 2048 + akb);
            #pragma unroll
            for (int nt = 0; nt < 4; ++nt)
                ldsm_x2(bfH[nt][0], bfH[nt][1], wb + bbase + nt * 1024 + bkb);
            #pragma unroll
            for (int mt = 0; mt < 2; ++mt)
                #pragma unroll
                for (int nt = 0; nt < 4; ++nt)
                    mma16816(acc[mt][nt], afH[mt], bfH[nt]);
            #pragma unroll
            for (int nt = 0; nt < 4; ++nt)
                ldsm_x2(bfL[nt][0], bfL[nt][1], wb + 16384 + bbase + nt * 1024 + bkb);
            #pragma unroll
            for (int mt = 0; mt < 2; ++mt)
                #pragma unroll
                for (int nt = 0; nt < 4; ++nt)
                    mma16816(acc[mt][nt], afH[mt], bfL[nt]);
            #pragma unroll
            for (int mt = 0; mt < 2; ++mt)
                ldsm_x4(afL[mt][0], afL[mt][1], afL[mt][2], afL[mt][3],
                        sb + P_FLO + abase + mt * 2048 + akb);
            #pragma unroll
            for (int mt = 0; mt < 2; ++mt)
                #pragma unroll
                for (int nt = 0; nt < 4; ++nt)
                    mma16816(acc[mt][nt], afL[mt], bfH[nt]);
        }
    }

    // charge: reduce over 4 threads sharing a row
    csum += __shfl_xor_sync(0xffffffffu, csum, 1);
    csum += __shfl_xor_sync(0xffffffffu, csum, 2);
    if ((t & 3) == 0) chRow[fr] = 1.f / (1.f + expf(-(csum + bch[0])));
    __syncthreads();

    const float nls = -0.125f * loc_p[0];
    const int g = lid >> 2, tg = lid & 3;
    #pragma unroll
    for (int mt = 0; mt < 2; ++mt) {
        #pragma unroll
        for (int half = 0; half < 2; ++half) {
            int il = wm * 32 + mt * 16 + g + half * 8;
            size_t row = (size_t)(rowBase + il);
            float cr = chRow[il];
            #pragma unroll
            for (int nt = 0; nt < 4; ++nt) {
                int jl = wn * 32 + nt * 8 + tg * 2;
                float sc = (jl < 64) ? (nls * cr) : cr;
                float c0 = acc[mt][nt][half * 2 + 0] * sc;
                float c1 = acc[mt][nt][half * 2 + 1] * sc;
                u32 h, l;
                split2(c0, c1, h, l);
                if (jl < 64) {
                    *(u32*)&g_Qhi[row * D_DIM + jl] = h;
                    *(u32*)&g_Qlo[row * D_DIM + jl] = l;
                } else {
                    *(u32*)&g_Khi[row * D_DIM + jl - 64] = h;
                    *(u32*)&g_Klo[row * D_DIM + jl - 64] = l;
                }
            }
        }
    }
}

// =================================================================
// energy: persistent, 4 CTAs/SM (128 threads), job tile 64(i) x 64(j)
// warp grid 2x2, warp tile 32x32; K double-buffered cp.async
// smem: Qhi 0(8K), Qlo 8K, Kbuf0 {hi 16K, lo 24K}, Kbuf1 {hi 32K, lo 40K}
// =================================================================
#define E_Q 0
#define E_K 16384
#define E_SMEM 49152

__global__ __launch_bounds__(128, 4) void energy_kernel(float* __restrict__ out)
{
    extern __shared__ char smem[];
    const u32 sb = smem_u32(smem);

    const int t = threadIdx.x;
    const int wid = t >> 5, lid = t & 31;
    const int wm = wid & 1, wn = wid >> 1;

    const int js = (int)(((long long)blockIdx.x * TOTAL_JOBS) / EGRID);
    const int je = (int)(((long long)(blockIdx.x + 1) * TOTAL_JOBS) / EGRID);

    const int lc16 = t & 7;
    const int row16 = t >> 3;     // + 16*l

    const u32 lxor  = ((u32)(lid & 7)) << 4;
    const u32 abase = (u32)((wm * 32) + (lid & 7) + ((lid >> 3) & 1) * 8) * 128;
    const u32 ach   = ((u32)(lid >> 4) & 1) * 16;
    const u32 bbase = (u32)((wn * 32) + (lid & 7)) * 128;
    const u32 bkh   = ((u32)(lid >> 3) & 1) * 16;

    // prefetch K for first job
    {
        int job = js;
        int ib = job >> 6;
        size_t krow0 = (size_t)(ib >> 6) * S_DIM + (size_t)(job & 63) * 64;
        u32 kb = sb + E_K;
        #pragma unroll
        for (int l = 0; l < 4; ++l) {
            int row = row16 + 16 * l;
            u32 off = (u32)row * 128 + (u32)lc16 * 16;
            u32 swo = off ^ ((off >> 3) & 0x70);
            cp16(kb + swo, (const char*)(g_Khi + (krow0 + row) * D_DIM) + lc16 * 16);
            cp16(kb + 8192 + swo, (const char*)(g_Klo + (krow0 + row) * D_DIM) + lc16 * 16);
        }
        cp_commit();
    }

    int curIb = -1;

    for (int job = js; job < je; ++job) {
        const int ib = job >> 6;
        const int jt = job & 63;
        const int buf = (job - js) & 1;
        const u32 kb = sb + E_K + buf * 16384;

        cp_wait0();
        __syncthreads();

        if (ib != curIb) {
            size_t qrow0 = (size_t)ib * 64;
            #pragma unroll
            for (int l = 0; l < 4; ++l) {
                int row = row16 + 16 * l;
                u32 off = (u32)row * 128 + (u32)lc16 * 16;
                u32 swo = off ^ ((off >> 3) & 0x70);
                *(uint4*)(smem + E_Q + swo) =
                    *(const uint4*)((const char*)(g_Qhi + (qrow0 + row) * D_DIM) + lc16 * 16);
                *(uint4*)(smem + E_Q + 8192 + swo) =
                    *(const uint4*)((const char*)(g_Qlo + (qrow0 + row) * D_DIM) + lc16 * 16);
            }
            curIb = ib;
            __syncthreads();
        }

        // prefetch next K (overlaps MMA)
        if (job + 1 < je) {
            int nj = job + 1;
            int nib = nj >> 6;
            size_t krow0 = (size_t)(nib >> 6) * S_DIM + (size_t)(nj & 63) * 64;
            u32 nkb = sb + E_K + (buf ^ 1) * 16384;
            #pragma unroll
            for (int l = 0; l < 4; ++l) {
                int row = row16 + 16 * l;
                u32 off = (u32)row * 128 + (u32)lc16 * 16;
                u32 swo = off ^ ((off >> 3) & 0x70);
                cp16(nkb + swo, (const char*)(g_Khi + (krow0 + row) * D_DIM) + lc16 * 16);
                cp16(nkb + 8192 + swo, (const char*)(g_Klo + (krow0 + row) * D_DIM) + lc16 * 16);
            }
            cp_commit();
        }

        // ---- fused 3-pass MMA, warp tile 32x32 ----
        float acc[2][4][4] = {};
        #pragma unroll
        for (int ks = 0; ks < 4; ++ks) {
            const u32 akb = ((u32)(ks * 32) + ach) ^ lxor;
            const u32 bkb = ((u32)(ks * 32) + bkh) ^ lxor;
            u32 afH[2][4], afL[2][4], bfH[4][2], bfL[4][2];
            #pragma unroll
            for (int mt = 0; mt < 2; ++mt)
                ldsm_x4(afH[mt][0], afH[mt][1], afH[mt][2], afH[mt][3],
                        sb + E_Q + abase + mt * 2048 + akb);
            #pragma unroll
            for (int nt = 0; nt < 4; ++nt)
                ldsm_x2(bfH[nt][0], bfH[nt][1], kb + bbase + nt * 1024 + bkb);
            #pragma unroll
            for (int mt = 0; mt < 2; ++mt)
                #pragma unroll
                for (int nt = 0; nt < 4; ++nt)
                    mma16816(acc[mt][nt], afH[mt], bfH[nt]);
            #pragma unroll
            for (int nt = 0; nt < 4; ++nt)
                ldsm_x2(bfL[nt][0], bfL[nt][1], kb + 8192 + bbase + nt * 1024 + bkb);
            #pragma unroll
            for (int mt = 0; mt < 2; ++mt)
                #pragma unroll
                for (int nt = 0; nt < 4; ++nt)
                    mma16816(acc[mt][nt], afH[mt], bfL[nt]);
            #pragma unroll
            for (int mt = 0; mt < 2; ++mt)
                ldsm_x4(afL[mt][0], afL[mt][1], afL[mt][2], afL[mt][3],
                        sb + E_Q + 8192 + abase + mt * 2048 + akb);
            #pragma unroll
            for (int mt = 0; mt < 2; ++mt)
                #pragma unroll
                for (int nt = 0; nt < 4; ++nt)
                    mma16816(acc[mt][nt], afL[mt], bfH[nt]);
        }

        // ---- epilogue ----
        const int iPos0 = (ib & 63) * 64;
        const int jj0 = jt * 64;
        const int g = lid >> 2, tg = lid & 3;
        float* ob = out + ((size_t)ib * 64) * S_DIM + jj0;
        #pragma unroll
        for (int mt = 0; mt < 2; ++mt) {
            #pragma unroll
            for (int half = 0; half < 2; ++half) {
                int il = wm * 32 + mt * 16 + g + half * 8;
                int ip = iPos0 + il;
                float* orow = ob + (size_t)il * S_DIM;
                #pragma unroll
                for (int nt = 0; nt < 4; ++nt) {
                    int jl = wn * 32 + nt * 8 + tg * 2;
                    int jp = jj0 + jl;
                    float d0 = fmaxf(fabsf((float)(ip - jp)), 1.f);
                    float d1 = fmaxf(fabsf((float)(ip - jp - 1)), 1.f);
                    float2 o;
                    o.x = acc[mt][nt][half * 2 + 0] * fast_rcp(d0);
                    o.y = acc[mt][nt][half * 2 + 1] * fast_rcp(d1);
                    *(float2*)(orow + jl) = o;
                }
            }
        }
    }
}

extern "C" void kernel_launch(void* const* d_in, const int* in_sizes, int n_in,
                              void* d_out, int out_size) {
    const float* feat = (const float*)d_in[0];
    const float* Wq   = (const float*)d_in[1];
    const float* Wk   = (const float*)d_in[2];
    const float* wch  = (const float*)d_in[3];
    const float* bch  = (const float*)d_in[4];
    const float* ls   = (const float*)d_in[5];
    float* out = (float*)d_out;

    cudaFuncSetAttribute(proj_kernel, cudaFuncAttributeMaxDynamicSharedMemorySize, P_SMEM);
    cudaFuncSetAttribute(energy_kernel, cudaFuncAttributeMaxDynamicSharedMemorySize, E_SMEM);

    wsetup_kernel<<<32, 256>>>(Wq, Wk);
    proj_kernel<<<(B_DIM * S_DIM) / 64, 256, P_SMEM>>>(feat, wch, bch, ls);
    energy_kernel<<<EGRID, 128, E_SMEM>>>(out);
}

// round 8
// speedup vs baseline: 3.1331x; 1.0201x over previous
#include <cuda_runtime.h>
#include <cuda_bf16.h>

#define B_DIM 4
#define S_DIM 4096
#define F_DIM 512
#define D_DIM 64
#define EGRID 608
#define TOTAL_JOBS 16384   // 256 i-blocks(64) x 64 j-tiles(64)

// ---------------- scratch (no cudaMalloc allowed) ----------------
__device__ __nv_bfloat16 g_Qhi[B_DIM * S_DIM * D_DIM];
__device__ __nv_bfloat16 g_Qlo[B_DIM * S_DIM * D_DIM];
__device__ __nv_bfloat16 g_Khi[B_DIM * S_DIM * D_DIM];
__device__ __nv_bfloat16 g_Klo[B_DIM * S_DIM * D_DIM];
__device__ unsigned char g_Whs[8 * 16384];   // pre-swizzled W hi tiles
__device__ unsigned char g_Wls[8 * 16384];   // pre-swizzled W lo tiles

typedef unsigned long long u64;
typedef unsigned u32;

__device__ __forceinline__ float fast_rcp(float x) {
    float r; asm("rcp.approx.f32 %0, %1;" : "=f"(r) : "f"(x)); return r;
}
__device__ __forceinline__ u32 smem_u32(const void* p) {
    u32 a;
    asm("{ .reg .u64 t; cvta.to.shared.u64 t, %1; cvt.u32.u64 %0, t; }" : "=r"(a) : "l"(p));
    return a;
}
__device__ __forceinline__ void ldsm_x4(u32& r0, u32& r1, u32& r2, u32& r3, u32 addr) {
    asm volatile("ldmatrix.sync.aligned.m8n8.x4.shared.b16 {%0,%1,%2,%3}, [%4];"
                 : "=r"(r0), "=r"(r1), "=r"(r2), "=r"(r3) : "r"(addr));
}
__device__ __forceinline__ void mma16816(float* c, const u32* a, const u32* b) {
    asm volatile(
        "mma.sync.aligned.m16n8k16.row.col.f32.bf16.bf16.f32 "
        "{%0,%1,%2,%3}, {%4,%5,%6,%7}, {%8,%9}, {%0,%1,%2,%3};"
        : "+f"(c[0]), "+f"(c[1]), "+f"(c[2]), "+f"(c[3])
        : "r"(a[0]), "r"(a[1]), "r"(a[2]), "r"(a[3]), "r"(b[0]), "r"(b[1]));
}
__device__ __forceinline__ void cp16(u32 dst, const void* src) {
    asm volatile("cp.async.cg.shared.global [%0], [%1], 16;" :: "r"(dst), "l"(src));
}
__device__ __forceinline__ void cp_commit() { asm volatile("cp.async.commit_group;" ::: "memory"); }
__device__ __forceinline__ void cp_wait0()  { asm volatile("cp.async.wait_group 0;" ::: "memory"); }
__device__ __forceinline__ void cp_wait1()  { asm volatile("cp.async.wait_group 1;" ::: "memory"); }

__device__ __forceinline__ void split2(float x, float y, u32& h, u32& l) {
    __nv_bfloat162 hh = __floats2bfloat162_rn(x, y);
    float rx = x - __bfloat162float(hh.x);
    float ry = y - __bfloat162float(hh.y);
    __nv_bfloat162 ll = __floats2bfloat162_rn(rx, ry);
    h = *(u32*)&hh; l = *(u32*)&ll;
}

// =================================================================
// W setup: split Wq|Wk to bf16 hi/lo pre-swizzled tile images
// =================================================================
__global__ __launch_bounds__(256) void wsetup_kernel(
    const float* __restrict__ Wq, const float* __restrict__ Wk)
{
    int idx = blockIdx.x * 256 + threadIdx.x;   // 8192 items
    int c = idx >> 10;
    int j = (idx >> 3) & 127;
    int a = idx & 7;
    const float* wp = (j < 64) ? (Wq + j) : (Wk + (j - 64));
    int f0 = c * 64 + a * 8;
    float wv[8];
    #pragma unroll
    for (int k = 0; k < 8; ++k) wv[k] = wp[(size_t)(f0 + k) * D_DIM];
    uint4 H, L;
    split2(wv[0], wv[1], H.x, L.x);
    split2(wv[2], wv[3], H.y, L.y);
    split2(wv[4], wv[5], H.z, L.z);
    split2(wv[6], wv[7], H.w, L.w);
    u32 off = (u32)j * 128 + (u32)a * 16;
    u32 swo = off ^ ((off >> 3) & 0x70);
    *(uint4*)(g_Whs + c * 16384 + swo) = H;
    *(uint4*)(g_Wls + c * 16384 + swo) = L;
}

// =================================================================
// proj: 64-row tiles, grid 256, 2 CTAs/SM. HMMA [64] x [128 = Q|K].
// B fragments via ldmatrix.x4 (2 n8-blocks per instr).
// =================================================================
#define P_FHI 0
#define P_FLO 8192
#define P_W   16384
#define P_WCS 81920
#define P_CHR 82432
#define P_SMEM 82944

__global__ __launch_bounds__(256, 2) void proj_kernel(
    const float* __restrict__ feat, const float* __restrict__ wch,
    const float* __restrict__ bch, const float* __restrict__ loc_p)
{
    extern __shared__ char smem[];
    const u32 sb = smem_u32(smem);
    float* wcs   = (float*)(smem + P_WCS);
    float* chRow = (float*)(smem + P_CHR);

    const int t = threadIdx.x;
    const int wid = t >> 5, lid = t & 31;
    const int wm = wid & 1, wn = wid >> 1;
    const int rowBase = blockIdx.x * 64;

    const int fr = t >> 2, ffo = (t & 3) * 16;
    const int watom = t * 16;

    if (t < 64) wcs[t] = wch[t];

    const u32 lxor  = ((u32)(lid & 7)) << 4;
    const u32 abase = (u32)((wm * 32) + (lid & 7) + ((lid >> 3) & 1) * 8) * 128;
    const u32 ach   = ((u32)(lid >> 4) & 1) * 16;
    const u32 bbase4 = (u32)((wn * 32) + ((lid >> 4) & 1) * 8 + (lid & 7)) * 128;
    const u32 bk4    = ((u32)(lid >> 3) & 1) * 16;

    float acc[2][4][4] = {};
    float csum = 0.f;

    // prefetch W chunk 0 into buf 0
    {
        u32 wb = sb + P_W;
        #pragma unroll
        for (int a = 0; a < 4; ++a) {
            cp16(wb + watom + a * 4096, g_Whs + watom + a * 4096);
            cp16(wb + 16384 + watom + a * 4096, g_Wls + watom + a * 4096);
        }
        cp_commit();
    }

    for (int c = 0; c < 8; ++c) {
        const int f0 = c * 64;
        const u32 wb = sb + P_W + (c & 1) * 32768;
        __syncthreads();
        const float* wc_cur = wcs + (c & 1) * 64;
        // ---- feat tile: 64 rows x 64 f, fp32 -> hi/lo + charge partial ----
        {
            const float* fp = feat + (size_t)(rowBase + fr) * F_DIM + f0 + ffo;
            #pragma unroll
            for (int a = 0; a < 2; ++a) {
                float4 v0 = *(const float4*)(fp + a * 8);
                float4 v1 = *(const float4*)(fp + a * 8 + 4);
                csum += v0.x * wc_cur[ffo + a*8 + 0] + v0.y * wc_cur[ffo + a*8 + 1]
                      + v0.z * wc_cur[ffo + a*8 + 2] + v0.w * wc_cur[ffo + a*8 + 3]
                      + v1.x * wc_cur[ffo + a*8 + 4] + v1.y * wc_cur[ffo + a*8 + 5]
                      + v1.z * wc_cur[ffo + a*8 + 6] + v1.w * wc_cur[ffo + a*8 + 7];
                uint4 H, L;
                split2(v0.x, v0.y, H.x, L.x);
                split2(v0.z, v0.w, H.y, L.y);
                split2(v1.x, v1.y, H.z, L.z);
                split2(v1.z, v1.w, H.w, L.w);
                u32 off = (u32)fr * 128 + (u32)(ffo + a * 8) * 2;
                u32 swo = off ^ ((off >> 3) & 0x70);
                *(uint4*)(smem + P_FHI + swo) = H;
                *(uint4*)(smem + P_FLO + swo) = L;
            }
        }
        // prefetch next W chunk
        if (c + 1 < 8) {
            u32 nwb = sb + P_W + ((c + 1) & 1) * 32768;
            const unsigned char* gh = g_Whs + (c + 1) * 16384;
            const unsigned char* gl = g_Wls + (c + 1) * 16384;
            #pragma unroll
            for (int a = 0; a < 4; ++a) {
                cp16(nwb + watom + a * 4096, gh + watom + a * 4096);
                cp16(nwb + 16384 + watom + a * 4096, gl + watom + a * 4096);
            }
            cp_commit();
            cp_wait1();
        } else {
            cp_wait0();
        }
        if (t < 64 && c + 1 < 8) wcs[((c + 1) & 1) * 64 + t] = wch[f0 + 64 + t];
        __syncthreads();

        // ---- fused 3-pass MMA, x4 B loads ----
        #pragma unroll
        for (int ks = 0; ks < 4; ++ks) {
            const u32 akb = ((u32)(ks * 32) + ach) ^ lxor;
            const u32 bkb = ((u32)(ks * 32) + bk4) ^ lxor;
            u32 afH[2][4], afL[2][4], bH[8], bL[8];
            #pragma unroll
            for (int mt = 0; mt < 2; ++mt)
                ldsm_x4(afH[mt][0], afH[mt][1], afH[mt][2], afH[mt][3],
                        sb + P_FHI + abase + mt * 2048 + akb);
            ldsm_x4(bH[0], bH[1], bH[2], bH[3], wb + bbase4 + bkb);
            ldsm_x4(bH[4], bH[5], bH[6], bH[7], wb + bbase4 + 2048 + bkb);
            #pragma unroll
            for (int mt = 0; mt < 2; ++mt)
                #pragma unroll
                for (int nt = 0; nt < 4; ++nt)
                    mma16816(acc[mt][nt], afH[mt], bH + nt * 2);
            ldsm_x4(bL[0], bL[1], bL[2], bL[3], wb + 16384 + bbase4 + bkb);
            ldsm_x4(bL[4], bL[5], bL[6], bL[7], wb + 16384 + bbase4 + 2048 + bkb);
            #pragma unroll
            for (int mt = 0; mt < 2; ++mt)
                #pragma unroll
                for (int nt = 0; nt < 4; ++nt)
                    mma16816(acc[mt][nt], afH[mt], bL + nt * 2);
            #pragma unroll
            for (int mt = 0; mt < 2; ++mt)
                ldsm_x4(afL[mt][0], afL[mt][1], afL[mt][2], afL[mt][3],
                        sb + P_FLO + abase + mt * 2048 + akb);
            #pragma unroll
            for (int mt = 0; mt < 2; ++mt)
                #pragma unroll
                for (int nt = 0; nt < 4; ++nt)
                    mma16816(acc[mt][nt], afL[mt], bH + nt * 2);
        }
    }

    csum += __shfl_xor_sync(0xffffffffu, csum, 1);
    csum += __shfl_xor_sync(0xffffffffu, csum, 2);
    if ((t & 3) == 0) chRow[fr] = 1.f / (1.f + expf(-(csum + bch[0])));
    __syncthreads();

    const float nls = -0.125f * loc_p[0];
    const int g = lid >> 2, tg = lid & 3;
    #pragma unroll
    for (int mt = 0; mt < 2; ++mt) {
        #pragma unroll
        for (int half = 0; half < 2; ++half) {
            int il = wm * 32 + mt * 16 + g + half * 8;
            size_t row = (size_t)(rowBase + il);
            float cr = chRow[il];
            #pragma unroll
            for (int nt = 0; nt < 4; ++nt) {
                int jl = wn * 32 + nt * 8 + tg * 2;
                float sc = (jl < 64) ? (nls * cr) : cr;
                float c0 = acc[mt][nt][half * 2 + 0] * sc;
                float c1 = acc[mt][nt][half * 2 + 1] * sc;
                u32 h, l;
                split2(c0, c1, h, l);
                if (jl < 64) {
                    *(u32*)&g_Qhi[row * D_DIM + jl] = h;
                    *(u32*)&g_Qlo[row * D_DIM + jl] = l;
                } else {
                    *(u32*)&g_Khi[row * D_DIM + jl - 64] = h;
                    *(u32*)&g_Klo[row * D_DIM + jl - 64] = l;
                }
            }
        }
    }
}

// =================================================================
// energy: persistent, 4 CTAs/SM (128 threads), job tile 64(i) x 64(j)
// A-hi fragments hoisted per i-block (reused 64 jobs); B via x4 LDSM.
// smem: Qhi 0(8K), Qlo 8K, Kbuf0 {hi 16K, lo 24K}, Kbuf1 {hi 32K, lo 40K}
// =================================================================
#define E_Q 0
#define E_K 16384
#define E_SMEM 49152

__global__ __launch_bounds__(128, 4) void energy_kernel(float* __restrict__ out)
{
    extern __shared__ char smem[];
    const u32 sb = smem_u32(smem);

    const int t = threadIdx.x;
    const int wid = t >> 5, lid = t & 31;
    const int wm = wid & 1, wn = wid >> 1;

    const int js = (int)(((long long)blockIdx.x * TOTAL_JOBS) / EGRID);
    const int je = (int)(((long long)(blockIdx.x + 1) * TOTAL_JOBS) / EGRID);

    const int lc16 = t & 7;
    const int row16 = t >> 3;     // + 16*l

    const u32 lxor  = ((u32)(lid & 7)) << 4;
    const u32 abase = (u32)((wm * 32) + (lid & 7) + ((lid >> 3) & 1) * 8) * 128;
    const u32 ach   = ((u32)(lid >> 4) & 1) * 16;
    const u32 bbase4 = (u32)((wn * 32) + ((lid >> 4) & 1) * 8 + (lid & 7)) * 128;
    const u32 bk4    = ((u32)(lid >> 3) & 1) * 16;

    // prefetch K for first job
    {
        int job = js;
        int ib = job >> 6;
        size_t krow0 = (size_t)(ib >> 6) * S_DIM + (size_t)(job & 63) * 64;
        u32 kb = sb + E_K;
        #pragma unroll
        for (int l = 0; l < 4; ++l) {
            int row = row16 + 16 * l;
            u32 off = (u32)row * 128 + (u32)lc16 * 16;
            u32 swo = off ^ ((off >> 3) & 0x70);
            cp16(kb + swo, (const char*)(g_Khi + (krow0 + row) * D_DIM) + lc16 * 16);
            cp16(kb + 8192 + swo, (const char*)(g_Klo + (krow0 + row) * D_DIM) + lc16 * 16);
        }
        cp_commit();
    }

    int curIb = -1;
    u32 afH[4][2][4];   // hoisted A-hi fragments: [ks][mt][4]

    for (int job = js; job < je; ++job) {
        const int ib = job >> 6;
        const int jt = job & 63;
        const int buf = (job - js) & 1;
        const u32 kb = sb + E_K + buf * 16384;

        cp_wait0();
        __syncthreads();

        if (ib != curIb) {
            size_t qrow0 = (size_t)ib * 64;
            #pragma unroll
            for (int l = 0; l < 4; ++l) {
                int row = row16 + 16 * l;
                u32 off = (u32)row * 128 + (u32)lc16 * 16;
                u32 swo = off ^ ((off >> 3) & 0x70);
                *(uint4*)(smem + E_Q + swo) =
                    *(const uint4*)((const char*)(g_Qhi + (qrow0 + row) * D_DIM) + lc16 * 16);
                *(uint4*)(smem + E_Q + 8192 + swo) =
                    *(const uint4*)((const char*)(g_Qlo + (qrow0 + row) * D_DIM) + lc16 * 16);
            }
            curIb = ib;
            __syncthreads();
            // extract A-hi fragments for all 4 k-steps into registers
            #pragma unroll
            for (int ks = 0; ks < 4; ++ks) {
                const u32 akb = ((u32)(ks * 32) + ach) ^ lxor;
                #pragma unroll
                for (int mt = 0; mt < 2; ++mt)
                    ldsm_x4(afH[ks][mt][0], afH[ks][mt][1], afH[ks][mt][2], afH[ks][mt][3],
                            sb + E_Q + abase + mt * 2048 + akb);
            }
        }

        // prefetch next K (overlaps MMA)
        if (job + 1 < je) {
            int nj = job + 1;
            int nib = nj >> 6;
            size_t krow0 = (size_t)(nib >> 6) * S_DIM + (size_t)(nj & 63) * 64;
            u32 nkb = sb + E_K + (buf ^ 1) * 16384;
            #pragma unroll
            for (int l = 0; l < 4; ++l) {
                int row = row16 + 16 * l;
                u32 off = (u32)row * 128 + (u32)lc16 * 16;
                u32 swo = off ^ ((off >> 3) & 0x70);
                cp16(nkb + swo, (const char*)(g_Khi + (krow0 + row) * D_DIM) + lc16 * 16);
                cp16(nkb + 8192 + swo, (const char*)(g_Klo + (krow0 + row) * D_DIM) + lc16 * 16);
            }
            cp_commit();
        }

        // ---- fused 3-pass MMA: afH hoisted, B via x4, aL per job ----
        float acc[2][4][4] = {};
        #pragma unroll
        for (int ks = 0; ks < 4; ++ks) {
            const u32 akb = ((u32)(ks * 32) + ach) ^ lxor;
            const u32 bkb = ((u32)(ks * 32) + bk4) ^ lxor;
            u32 bH[8], bL[8], aL[2][4];
            ldsm_x4(bH[0], bH[1], bH[2], bH[3], kb + bbase4 + bkb);
            ldsm_x4(bH[4], bH[5], bH[6], bH[7], kb + bbase4 + 2048 + bkb);
            #pragma unroll
            for (int mt = 0; mt < 2; ++mt)
                #pragma unroll
                for (int nt = 0; nt < 4; ++nt)
                    mma16816(acc[mt][nt], afH[ks][mt], bH + nt * 2);
            ldsm_x4(bL[0], bL[1], bL[2], bL[3], kb + 8192 + bbase4 + bkb);
            ldsm_x4(bL[4], bL[5], bL[6], bL[7], kb + 8192 + bbase4 + 2048 + bkb);
            #pragma unroll
            for (int mt = 0; mt < 2; ++mt)
                #pragma unroll
                for (int nt = 0; nt < 4; ++nt)
                    mma16816(acc[mt][nt], afH[ks][mt], bL + nt * 2);
            #pragma unroll
            for (int mt = 0; mt < 2; ++mt)
                ldsm_x4(aL[mt][0], aL[mt][1], aL[mt][2], aL[mt][3],
                        sb + E_Q + 8192 + abase + mt * 2048 + akb);
            #pragma unroll
            for (int mt = 0; mt < 2; ++mt)
                #pragma unroll
                for (int nt = 0; nt < 4; ++nt)
                    mma16816(acc[mt][nt], aL[mt], bH + nt * 2);
        }

        // ---- epilogue ----
        const int iPos0 = (ib & 63) * 64;
        const int jj0 = jt * 64;
        const int g = lid >> 2, tg = lid & 3;
        float* ob = out + ((size_t)ib * 64) * S_DIM + jj0;
        #pragma unroll
        for (int mt = 0; mt < 2; ++mt) {
            #pragma unroll
            for (int half = 0; half < 2; ++half) {
                int il = wm * 32 + mt * 16 + g + half * 8;
                int ip = iPos0 + il;
                float* orow = ob + (size_t)il * S_DIM;
                #pragma unroll
                for (int nt = 0; nt < 4; ++nt) {
                    int jl = wn * 32 + nt * 8 + tg * 2;
                    int jp = jj0 + jl;
                    float d0 = fmaxf(fabsf((float)(ip - jp)), 1.f);
                    float d1 = fmaxf(fabsf((float)(ip - jp - 1)), 1.f);
                    float2 o;
                    o.x = acc[mt][nt][half * 2 + 0] * fast_rcp(d0);
                    o.y = acc[mt][nt][half * 2 + 1] * fast_rcp(d1);
                    *(float2*)(orow + jl) = o;
                }
            }
        }
    }
}

extern "C" void kernel_launch(void* const* d_in, const int* in_sizes, int n_in,
                              void* d_out, int out_size) {
    const float* feat = (const float*)d_in[0];
    const float* Wq   = (const float*)d_in[1];
    const float* Wk   = (const float*)d_in[2];
    const float* wch  = (const float*)d_in[3];
    const float* bch  = (const float*)d_in[4];
    const float* ls   = (const float*)d_in[5];
    float* out = (float*)d_out;

    cudaFuncSetAttribute(proj_kernel, cudaFuncAttributeMaxDynamicSharedMemorySize, P_SMEM);
    cudaFuncSetAttribute(energy_kernel, cudaFuncAttributeMaxDynamicSharedMemorySize, E_SMEM);

    wsetup_kernel<<<32, 256>>>(Wq, Wk);
    proj_kernel<<<(B_DIM * S_DIM) / 64, 256, P_SMEM>>>(feat, wch, bch, ls);
    energy_kernel<<<EGRID, 128, E_SMEM>>>(out);
}